// round 5
// baseline (speedup 1.0000x reference)
#include <cuda_runtime.h>

#define NQ 512
#define ND 256
#define NF 50
#define QP 52
#define STP 260
#define TTP 261
#define NOUT 200

typedef unsigned long long u64;
typedef unsigned int u32;

// ---------------- global scratch (no allocations) ----------------
__device__ float g_S  [67108864];  // [b][j][i] S, overwritten with E1=exp(S-colmax)
__device__ float g_E2 [67108864];  // [b][i][j] E2=exp(S-rowmax)
__device__ float g_T  [13631488];  // [b][j][52]
__device__ float g_senT[6815744];  // [b][52][256]: rows0..49 sen^T*w3, row50 senw1, row51 ones
__device__ float g_qpad[26624];    // [512][52]: cols0..49 q, col50=1, col51=qterm
__device__ float g_rowhalf[262144];// [b][2][256] rowmax partials
__device__ float g_colmax [262144];// [b][512]
__device__ float g_rowinv [131072];// [b][256]
__device__ float g_colinv [262144];// [b][512]

// ---------------- helpers ----------------
__device__ __forceinline__ u64 pack2(float x, float y) {
    u64 r; asm("mov.b64 %0, {%1, %2};" : "=l"(r) : "f"(x), "f"(y)); return r;
}
__device__ __forceinline__ u64 fma2(u64 a, u64 b, u64 c) {
    u64 d; asm("fma.rn.f32x2 %0, %1, %2, %3;" : "=l"(d) : "l"(a), "l"(b), "l"(c)); return d;
}
__device__ __forceinline__ float2 unpack2(u64 v) {
    float lo, hi; asm("mov.b64 {%0, %1}, %2;" : "=f"(lo), "=f"(hi) : "l"(v));
    return make_float2(lo, hi);
}
// order-preserving float<->uint for atomicMax
__device__ __forceinline__ u32 fenc(float f) {
    u32 u = __float_as_uint(f);
    return (u & 0x80000000u) ? ~u : (u | 0x80000000u);
}
__device__ __forceinline__ float fdec(u32 e) {
    return __uint_as_float((e & 0x80000000u) ? (e & 0x7FFFFFFFu) : ~e);
}

// ================= K_prep: senT + qpad =================
__global__ __launch_bounds__(256)
void k_prep(const float* __restrict__ q, const float* __restrict__ doc,
            const float* __restrict__ W)
{
    const int b = blockIdx.x, tid = threadIdx.x;
    if (b >= 512) {                       // qpad blocks (b = 512, 513)
        const int j = (b - 512) * 256 + tid;
        float qr[NF];
        #pragma unroll
        for (int k = 0; k < NF; k++) qr[k] = __ldg(q + j*NF + k);
        float a = 0.f;
        #pragma unroll
        for (int k = 0; k < NF; k++) a += qr[k] * __ldg(W + 50 + k);
        float* dst = g_qpad + j*QP;
        #pragma unroll
        for (int k = 0; k < NF; k++) dst[k] = qr[k];
        dst[50] = 1.0f; dst[51] = a;
        return;
    }
    extern __shared__ float sp[];
    float* s_sen = sp;            // [256*50]
    float* s_w   = sp + ND*NF;    // [152]
    if (tid < 150) s_w[tid] = W[tid];
    for (int idx = tid; idx < ND*NF; idx += 256) s_sen[idx] = doc[(size_t)b*ND*NF + idx];
    __syncthreads();
    float* dst = g_senT + (size_t)b * 52 * 256;
    for (int idx = tid; idx < 50*256; idx += 256) {
        const int k = idx >> 8, i = idx & 255;
        dst[idx] = s_sen[i*NF + k] * s_w[100 + k];
    }
    float a = 0.f;
    #pragma unroll
    for (int k = 0; k < NF; k++) a += s_sen[tid*NF + k] * s_w[k];
    dst[50*256 + tid] = a;
    dst[51*256 + tid] = 1.0f;
}

// ================= K1: S GEMM + fused max stats =================
// grid 1024 (b*2+half), block 256, 2 CTAs/SM
__global__ __launch_bounds__(256, 2)
void k_gemm()
{
    extern __shared__ float sm[];
    float* s_senT = sm;                        // [52][STP]
    float* s_qh   = sm + 52*STP;               // [256][QP] (this j-half)
    u32*   s_cmax = (u32*)(s_qh + 256*QP);     // [256]
    u32*   s_rmax = s_cmax + 256;              // [256]

    const int tid  = threadIdx.x;
    const int b    = blockIdx.x >> 1, half = blockIdx.x & 1;

    // load senT coalesced
    for (int x = tid; x < 52*64; x += 256) {
        const int k = x >> 6, c = x & 63;
        *(float4*)(s_senT + k*STP + c*4) =
            *(const float4*)(g_senT + (size_t)b*13312 + k*256 + c*4);
    }
    // load q half
    for (int x = tid; x < 256*13; x += 256) {
        const int jl = x / 13, c = x - jl*13;
        *(float4*)(s_qh + jl*QP + c*4) =
            *(const float4*)(g_qpad + (half*256 + jl)*QP + c*4);
    }
    if (tid < 256) { s_cmax[tid] = 0u; s_rmax[tid] = 0u; }
    __syncthreads();

    const int lane = tid & 31, w = tid >> 5;
    const int li = lane >> 3, lj = lane & 7;
    const int i0 = w*32 + li*8;                // warp w owns i-block w
    float* Sb = g_S + (size_t)b * NQ * ND;

    float rmax[8];
    #pragma unroll
    for (int u = 0; u < 8; u++) rmax[u] = -3.0e38f;

    for (int t = 0; t < 4; t++) {              // warp j-block = t
        const int j0l = t*64 + lj*8;           // local j (within half)
        u64 acc[8][4];
        #pragma unroll
        for (int jj = 0; jj < 8; jj++)
            #pragma unroll
            for (int m = 0; m < 4; m++) acc[jj][m] = 0ull;

        #pragma unroll 2
        for (int k = 0; k < 52; k += 2) {
            const ulonglong2 a00 = *(const ulonglong2*)(s_senT + k*STP + i0);
            const ulonglong2 a01 = *(const ulonglong2*)(s_senT + k*STP + i0 + 4);
            const ulonglong2 a10 = *(const ulonglong2*)(s_senT + (k+1)*STP + i0);
            const ulonglong2 a11 = *(const ulonglong2*)(s_senT + (k+1)*STP + i0 + 4);
            #pragma unroll
            for (int jj = 0; jj < 8; jj++) {
                const float2 qf = *(const float2*)(s_qh + (j0l + jj)*QP + k);
                const u64 b0 = pack2(qf.x, qf.x);
                const u64 b1 = pack2(qf.y, qf.y);
                acc[jj][0] = fma2(a00.x, b0, acc[jj][0]);
                acc[jj][1] = fma2(a00.y, b0, acc[jj][1]);
                acc[jj][2] = fma2(a01.x, b0, acc[jj][2]);
                acc[jj][3] = fma2(a01.y, b0, acc[jj][3]);
                acc[jj][0] = fma2(a10.x, b1, acc[jj][0]);
                acc[jj][1] = fma2(a10.y, b1, acc[jj][1]);
                acc[jj][2] = fma2(a11.x, b1, acc[jj][2]);
                acc[jj][3] = fma2(a11.y, b1, acc[jj][3]);
            }
        }
        #pragma unroll
        for (int jj = 0; jj < 8; jj++) {
            const int jg = half*256 + j0l + jj;
            ulonglong2 v0; v0.x = acc[jj][0]; v0.y = acc[jj][1];
            ulonglong2 v1; v1.x = acc[jj][2]; v1.y = acc[jj][3];
            *(ulonglong2*)(Sb + (size_t)jg*ND + i0)     = v0;
            *(ulonglong2*)(Sb + (size_t)jg*ND + i0 + 4) = v1;
            const float2 f0 = unpack2(acc[jj][0]);
            const float2 f1 = unpack2(acc[jj][1]);
            const float2 f2 = unpack2(acc[jj][2]);
            const float2 f3 = unpack2(acc[jj][3]);
            // colmax over this thread's 8 i
            float cm = fmaxf(fmaxf(fmaxf(f0.x, f0.y), fmaxf(f1.x, f1.y)),
                             fmaxf(fmaxf(f2.x, f2.y), fmaxf(f3.x, f3.y)));
            atomicMax(&s_cmax[j0l + jj], fenc(cm));
            // rowmax running over jj / t
            rmax[0] = fmaxf(rmax[0], f0.x); rmax[1] = fmaxf(rmax[1], f0.y);
            rmax[2] = fmaxf(rmax[2], f1.x); rmax[3] = fmaxf(rmax[3], f1.y);
            rmax[4] = fmaxf(rmax[4], f2.x); rmax[5] = fmaxf(rmax[5], f2.y);
            rmax[6] = fmaxf(rmax[6], f3.x); rmax[7] = fmaxf(rmax[7], f3.y);
        }
    }
    #pragma unroll
    for (int u = 0; u < 8; u++) atomicMax(&s_rmax[i0 + u], fenc(rmax[u]));
    __syncthreads();
    if (tid < 256) {
        g_colmax[b*512 + half*256 + tid]     = fdec(s_cmax[tid]);
        g_rowhalf[(b*2 + half)*256 + tid]    = fdec(s_rmax[tid]);
    }
}

// ================= K2: fused softmax transform =================
// grid 512, block 512: E1 in place, E2 transposed, rowsum, colsum
__global__ __launch_bounds__(512)
void k_soft()
{
    extern __shared__ float sm[];
    float* tile   = sm;                 // [32][TTP]
    float* s_cmax = sm + 32*TTP;        // [512]
    float* s_rmax = s_cmax + 512;       // [256]
    float* s_csum = s_rmax + 256;       // [512]
    float* s_red  = s_csum + 512;       // [512]

    const int tid = threadIdx.x, b = blockIdx.x;
    if (tid < 512) { s_cmax[tid] = g_colmax[b*512 + tid]; s_csum[tid] = 0.f; }
    if (tid < 256)
        s_rmax[tid] = fmaxf(g_rowhalf[(2*b)*256 + tid], g_rowhalf[(2*b+1)*256 + tid]);
    __syncthreads();

    const int i = tid & 255, hh = tid >> 8;
    const int lane = tid & 31, w = tid >> 5;
    const int rr = lane >> 3, f4 = lane & 7;
    const float rm = s_rmax[i];
    float rsum = 0.f;
    float* Sb = g_S  + (size_t)b * NQ * ND;
    float* E2 = g_E2 + (size_t)b * ND * NQ;

    for (int jc = 0; jc < 16; jc++) {
        #pragma unroll
        for (int jj = 0; jj < 16; jj++) {
            const int jp = hh*16 + jj, j = jc*32 + jp;
            const float v  = Sb[(size_t)j*ND + i];
            const float e1 = __expf(v - s_cmax[j]);
            const float e2 = __expf(v - rm);
            Sb[(size_t)j*ND + i] = e1;
            rsum += e2;
            tile[jp*TTP + i] = e2;
            // colsum: all 32 lanes share j -> warp reduce then one atomic
            float cs = e1;
            #pragma unroll
            for (int o = 16; o > 0; o >>= 1) cs += __shfl_xor_sync(0xffffffffu, cs, o);
            if (lane == 0) atomicAdd(&s_csum[j], cs);
        }
        __syncthreads();
        #pragma unroll
        for (int it = 0; it < 4; it++) {
            const int row = it*64 + w*4 + rr;
            float4 v;
            v.x = tile[(f4*4+0)*TTP + row];
            v.y = tile[(f4*4+1)*TTP + row];
            v.z = tile[(f4*4+2)*TTP + row];
            v.w = tile[(f4*4+3)*TTP + row];
            *(float4*)(E2 + (size_t)row*NQ + jc*32 + f4*4) = v;
        }
        __syncthreads();
    }
    s_red[tid] = rsum;
    __syncthreads();
    if (tid < 256) g_rowinv[b*256 + tid] = 1.0f / (s_red[tid] + s_red[tid + 256]);
    g_colinv[b*512 + tid] = 1.0f / s_csum[tid];
}

// ================= K3: T[j][k] = sum_i (E2[i][j]*rowinv[i]) * sen[i][k] =================
__global__ __launch_bounds__(512)
void k_T(const float* __restrict__ doc)
{
    extern __shared__ float sm[];
    float* s_sen  = sm;            // [256][QP]
    float* s_rinv = sm + ND*QP;    // [256]
    const int tid = threadIdx.x, b = blockIdx.x;

    for (int idx = tid; idx < ND*NF; idx += 512) {
        const int i = idx / NF, k = idx - i*NF;
        s_sen[i*QP + k] = doc[(size_t)b*ND*NF + idx];
    }
    if (tid < 256) { s_sen[tid*QP+50] = 0.f; s_sen[tid*QP+51] = 0.f; s_rinv[tid] = g_rowinv[b*256 + tid]; }
    __syncthreads();

    const float* E2 = g_E2 + (size_t)b * ND * NQ;
    float* Tg = g_T + (size_t)b * NQ * QP;

    const int jp = tid >> 1, h = tid & 1;
    const int koff = h ? 24 : 0;
    const int j0 = jp, j1 = jp + 256;
    u64 accA[14], accB[14];
    #pragma unroll
    for (int d = 0; d < 14; d++) { accA[d] = 0ull; accB[d] = 0ull; }

    #pragma unroll 2
    for (int i = 0; i < ND; i++) {
        const float rinv = s_rinv[i];
        const float p0 = E2[(size_t)i*NQ + j0] * rinv;
        const float p1 = E2[(size_t)i*NQ + j1] * rinv;
        const u64 b0 = pack2(p0, p0);
        const u64 b1 = pack2(p1, p1);
        const ulonglong2* srow = (const ulonglong2*)(s_sen + i*QP + koff);
        #pragma unroll
        for (int c = 0; c < 7; c++) {
            const ulonglong2 sv = srow[c];
            accA[2*c+0] = fma2(sv.x, b0, accA[2*c+0]);
            accA[2*c+1] = fma2(sv.y, b0, accA[2*c+1]);
            accB[2*c+0] = fma2(sv.x, b1, accB[2*c+0]);
            accB[2*c+1] = fma2(sv.y, b1, accB[2*c+1]);
        }
    }
    if (h == 0) {
        #pragma unroll
        for (int c = 0; c < 7; c++) {
            ulonglong2 vA; vA.x = accA[2*c]; vA.y = accA[2*c+1];
            ulonglong2 vB; vB.x = accB[2*c]; vB.y = accB[2*c+1];
            *(ulonglong2*)(Tg + j0*QP + 4*c) = vA;
            *(ulonglong2*)(Tg + j1*QP + 4*c) = vB;
        }
    } else {
        #pragma unroll
        for (int c = 0; c < 6; c++) {
            ulonglong2 vA; vA.x = accA[2+2*c]; vA.y = accA[3+2*c];
            ulonglong2 vB; vB.x = accB[2+2*c]; vB.y = accB[3+2*c];
            *(ulonglong2*)(Tg + j0*QP + 28 + 4*c) = vA;
            *(ulonglong2*)(Tg + j1*QP + 28 + 4*c) = vB;
        }
    }
}

// ================= K4: fused aD2Q/aQ2D GEMM + epilogue =================
__global__ __launch_bounds__(512)
void k_out(const float* __restrict__ doc, float* __restrict__ out)
{
    extern __shared__ float sm[];
    float* tile   = sm;                 // [32][STP]
    float* s_sen  = sm + 32*STP;        // [256][QP]
    float* s_cinv = s_sen + ND*QP;      // [512]
    const int tid = threadIdx.x, b = blockIdx.x;

    for (int idx = tid; idx < ND*NF; idx += 512) {
        const int i = idx / NF, k = idx - i*NF;
        s_sen[i*QP + k] = doc[(size_t)b*ND*NF + idx];
    }
    if (tid < 256) { s_sen[tid*QP+50] = 0.f; s_sen[tid*QP+51] = 0.f; }
    s_cinv[tid] = g_colinv[b*512 + tid];
    __syncthreads();

    const float* Sb = g_S + (size_t)b * NQ * ND;   // E1
    const float* Tb = g_T + (size_t)b * NQ * QP;

    const int ig = tid >> 4, kg = tid & 15;
    const int i0 = ig * 8;
    const int si = tid & 255, hh = tid >> 8;
    u64 ac1[4][4], ac2[4][4];
    #pragma unroll
    for (int k = 0; k < 4; k++)
        #pragma unroll
        for (int m = 0; m < 4; m++) { ac1[k][m] = 0ull; ac2[k][m] = 0ull; }

    for (int jc = 0; jc < 16; jc++) {
        #pragma unroll
        for (int jj = 0; jj < 16; jj++) {
            const int jp = hh*16 + jj, jg = jc*32 + jp;
            tile[jp*STP + si] = Sb[(size_t)jg*ND + si] * s_cinv[jg];
        }
        __syncthreads();
        if (kg < 13) {
            #pragma unroll 2
            for (int jj = 0; jj < 32; jj++) {
                const int j = jc*32 + jj;
                const ulonglong2 p01 = *(const ulonglong2*)(tile + jj*STP + i0);
                const ulonglong2 p23 = *(const ulonglong2*)(tile + jj*STP + i0 + 4);
                const u64 pa0 = p01.x, pa1 = p01.y, pa2 = p23.x, pa3 = p23.y;
                const float4 qv = __ldg((const float4*)(g_qpad + j*QP + kg*4));
                const float4 tv = __ldg((const float4*)(Tb + j*QP + kg*4));
                u64 bb;
                bb = pack2(qv.x, qv.x);
                ac1[0][0]=fma2(pa0,bb,ac1[0][0]); ac1[0][1]=fma2(pa1,bb,ac1[0][1]);
                ac1[0][2]=fma2(pa2,bb,ac1[0][2]); ac1[0][3]=fma2(pa3,bb,ac1[0][3]);
                bb = pack2(qv.y, qv.y);
                ac1[1][0]=fma2(pa0,bb,ac1[1][0]); ac1[1][1]=fma2(pa1,bb,ac1[1][1]);
                ac1[1][2]=fma2(pa2,bb,ac1[1][2]); ac1[1][3]=fma2(pa3,bb,ac1[1][3]);
                bb = pack2(qv.z, qv.z);
                ac1[2][0]=fma2(pa0,bb,ac1[2][0]); ac1[2][1]=fma2(pa1,bb,ac1[2][1]);
                ac1[2][2]=fma2(pa2,bb,ac1[2][2]); ac1[2][3]=fma2(pa3,bb,ac1[2][3]);
                bb = pack2(qv.w, qv.w);
                ac1[3][0]=fma2(pa0,bb,ac1[3][0]); ac1[3][1]=fma2(pa1,bb,ac1[3][1]);
                ac1[3][2]=fma2(pa2,bb,ac1[3][2]); ac1[3][3]=fma2(pa3,bb,ac1[3][3]);
                bb = pack2(tv.x, tv.x);
                ac2[0][0]=fma2(pa0,bb,ac2[0][0]); ac2[0][1]=fma2(pa1,bb,ac2[0][1]);
                ac2[0][2]=fma2(pa2,bb,ac2[0][2]); ac2[0][3]=fma2(pa3,bb,ac2[0][3]);
                bb = pack2(tv.y, tv.y);
                ac2[1][0]=fma2(pa0,bb,ac2[1][0]); ac2[1][1]=fma2(pa1,bb,ac2[1][1]);
                ac2[1][2]=fma2(pa2,bb,ac2[1][2]); ac2[1][3]=fma2(pa3,bb,ac2[1][3]);
                bb = pack2(tv.z, tv.z);
                ac2[2][0]=fma2(pa0,bb,ac2[2][0]); ac2[2][1]=fma2(pa1,bb,ac2[2][1]);
                ac2[2][2]=fma2(pa2,bb,ac2[2][2]); ac2[2][3]=fma2(pa3,bb,ac2[2][3]);
                bb = pack2(tv.w, tv.w);
                ac2[3][0]=fma2(pa0,bb,ac2[3][0]); ac2[3][1]=fma2(pa1,bb,ac2[3][1]);
                ac2[3][2]=fma2(pa2,bb,ac2[3][2]); ac2[3][3]=fma2(pa3,bb,ac2[3][3]);
            }
        }
        __syncthreads();
    }

    if (kg < 13) {
        #pragma unroll
        for (int m = 0; m < 4; m++) {
            float2 u1[4], u2[4];
            #pragma unroll
            for (int k = 0; k < 4; k++) { u1[k] = unpack2(ac1[k][m]); u2[k] = unpack2(ac2[k][m]); }
            #pragma unroll
            for (int par = 0; par < 2; par++) {
                const int i = i0 + 2*m + par;
                float a1v[4], a2v[4];
                #pragma unroll
                for (int k = 0; k < 4; k++) {
                    a1v[k] = par ? u1[k].y : u1[k].x;
                    a2v[k] = par ? u2[k].y : u2[k].x;
                }
                const float4 sv = *(const float4*)(s_sen + i*QP + kg*4);
                float* orow = out + ((size_t)b*ND + i) * NOUT;
                if (kg < 12) {
                    *(float4*)(orow + kg*4) = sv;
                    *(float2*)(orow +  50 + kg*4) = make_float2(a1v[0], a1v[1]);
                    *(float2*)(orow +  52 + kg*4) = make_float2(a1v[2], a1v[3]);
                    float4 p2; p2.x = sv.x*a1v[0]; p2.y = sv.y*a1v[1];
                               p2.z = sv.z*a1v[2]; p2.w = sv.w*a1v[3];
                    *(float4*)(orow + 100 + kg*4) = p2;
                    *(float2*)(orow + 150 + kg*4) = make_float2(sv.x*a2v[0], sv.y*a2v[1]);
                    *(float2*)(orow + 152 + kg*4) = make_float2(sv.z*a2v[2], sv.w*a2v[3]);
                } else {
                    *(float2*)(orow +  48) = make_float2(sv.x, sv.y);
                    *(float2*)(orow +  98) = make_float2(a1v[0], a1v[1]);
                    *(float2*)(orow + 148) = make_float2(sv.x*a1v[0], sv.y*a1v[1]);
                    *(float2*)(orow + 198) = make_float2(sv.x*a2v[0], sv.y*a2v[1]);
                }
            }
        }
    }
}

// ================= launch =================
extern "C" void kernel_launch(void* const* d_in, const int* in_sizes, int n_in,
                              void* d_out, int out_size)
{
    const float* query = nullptr;
    const float* doc   = nullptr;
    const float* Wp    = nullptr;
    for (int i = 0; i < n_in; i++) {
        if      (in_sizes[i] == 150)     Wp    = (const float*)d_in[i];
        else if (in_sizes[i] == NQ*NF)   query = (const float*)d_in[i];
        else                             doc   = (const float*)d_in[i];
    }

    const int smP = (ND*NF + 152) * 4;                          // 51.8 KB
    const int sm1 = (52*STP + 256*QP + 512) * 4;                // 109.4 KB
    const int sm2 = (32*TTP + 512 + 256 + 512 + 512) * 4;       // 40.6 KB
    const int sm3 = (ND*QP + 256) * 4;                          // 54.3 KB
    const int sm4 = (32*STP + ND*QP + 512) * 4;                 // 88.6 KB

    static bool attr_done = false;
    if (!attr_done) {
        cudaFuncSetAttribute(k_prep, cudaFuncAttributeMaxDynamicSharedMemorySize, smP);
        cudaFuncSetAttribute(k_gemm, cudaFuncAttributeMaxDynamicSharedMemorySize, sm1);
        cudaFuncSetAttribute(k_soft, cudaFuncAttributeMaxDynamicSharedMemorySize, sm2);
        cudaFuncSetAttribute(k_T,    cudaFuncAttributeMaxDynamicSharedMemorySize, sm3);
        cudaFuncSetAttribute(k_out,  cudaFuncAttributeMaxDynamicSharedMemorySize, sm4);
        attr_done = true;
    }

    k_prep<<<514, 256, smP>>>(query, doc, Wp);
    k_gemm<<<1024, 256, sm1>>>();
    k_soft<<<512, 512, sm2>>>();
    k_T   <<<512, 512, sm3>>>(doc);
    k_out <<<512, 512, sm4>>>(doc, (float*)d_out);
}

// round 7
// speedup vs baseline: 1.2433x; 1.2433x over previous
#include <cuda_runtime.h>

#define NQ 512
#define ND 256
#define NF 50
#define QP 52
#define STP 260
#define NOUT 200

typedef unsigned long long u64;
typedef unsigned int u32;

// ---------------- global scratch (no allocations) ----------------
__device__ float g_S   [67108864];  // [b][j][i] S col-major; later E1*colinv in place
__device__ float g_T   [13631488];  // [b][j][52]
__device__ float g_qpad[26624];     // [512][52]: cols0..49 q, col50=1, col51=qterm

// ---------------- helpers ----------------
__device__ __forceinline__ u64 pack2(float x, float y) {
    u64 r; asm("mov.b64 %0, {%1, %2};" : "=l"(r) : "f"(x), "f"(y)); return r;
}
__device__ __forceinline__ u64 fma2(u64 a, u64 b, u64 c) {
    u64 d; asm("fma.rn.f32x2 %0, %1, %2, %3;" : "=l"(d) : "l"(a), "l"(b), "l"(c)); return d;
}
__device__ __forceinline__ float2 unpack2(u64 v) {
    float lo, hi; asm("mov.b64 {%0, %1}, %2;" : "=f"(lo), "=f"(hi) : "l"(v));
    return make_float2(lo, hi);
}
__device__ __forceinline__ u32 fenc(float f) {
    u32 u = __float_as_uint(f);
    return (u & 0x80000000u) ? ~u : (u | 0x80000000u);
}
__device__ __forceinline__ float fdec(u32 e) {
    return __uint_as_float((e & 0x80000000u) ? (e & 0x7FFFFFFFu) : ~e);
}

// ================= K_prep: padded q with qterm fold =================
__global__ __launch_bounds__(256)
void k_prep(const float* __restrict__ q, const float* __restrict__ W)
{
    const int j = blockIdx.x * 256 + threadIdx.x;
    float qr[NF];
    #pragma unroll
    for (int k = 0; k < NF; k++) qr[k] = __ldg(q + j*NF + k);
    float a = 0.f;
    #pragma unroll
    for (int k = 0; k < NF; k++) a += qr[k] * __ldg(W + 50 + k);
    float* dst = g_qpad + j*QP;
    #pragma unroll
    for (int k = 0; k < NF; k++) dst[k] = qr[k];
    dst[50] = 1.0f; dst[51] = a;
}

// ================= main monolith: 256 threads, 2 CTAs/SM =================
#define SMEM_FLOATS (52*STP + ND*QP + 152 + 512 + 256 + 256 + 256)
#define SMEM_BYTES  (SMEM_FLOATS * 4)

__global__ __launch_bounds__(256, 2)
void cross_attn_main(const float* __restrict__ doc, const float* __restrict__ W,
                     float* __restrict__ out)
{
    extern __shared__ float sm[];
    float* s_senT = sm;                       // [52][STP]
    float* s_sen  = sm + 52*STP;              // [256][QP]
    float* s_w    = s_sen + ND*QP;            // [152]
    u32*   s_cmax = (u32*)(s_w + 152);        // [512]
    u32*   s_rmax = s_cmax + 512;             // [256]
    float* s_rmf  = (float*)(s_rmax + 256);   // [256]
    float* s_rinv = s_rmf + 256;              // [256]

    const int tid = threadIdx.x;
    const int b   = blockIdx.x;
    float* Sb = g_S + (size_t)b * NQ * ND;
    float* Tb = g_T + (size_t)b * NQ * QP;

    // ---------------- load phase ----------------
    if (tid < 150) s_w[tid] = __ldg(W + tid);
    for (int idx = tid; idx < ND*NF; idx += 256) {
        const int i = idx / NF, k = idx - i*NF;
        s_sen[i*QP + k] = doc[(size_t)b*ND*NF + idx];
    }
    { s_sen[tid*QP + 50] = 0.f; s_sen[tid*QP + 51] = 0.f; }
    { s_cmax[tid] = 0u; s_cmax[tid + 256] = 0u; s_rmax[tid] = 0u; }
    __syncthreads();

    // senT rows 0..49 (w3-folded); row50 = senw1; row51 = ones
    for (int idx = tid; idx < 50*256; idx += 256) {
        const int k = idx >> 8, i = idx & 255;
        s_senT[k*STP + i] = s_sen[i*QP + k] * s_w[100 + k];
    }
    {
        const int i = tid;
        float a = 0.f;
        #pragma unroll
        for (int k = 0; k < NF; k++) a += s_sen[i*QP + k] * s_w[k];
        s_senT[50*STP + i] = a;
        s_senT[51*STP + i] = 1.0f;
    }
    __syncthreads();

    // ---------------- pass 1: S GEMM + fused row/col max ----------------
    // warp w: i-block w*32; lane: li=lane>>3 (8 i), lj=lane&7 (8 j)
    {
        const int lane = tid & 31, w = tid >> 5;
        const int li = lane >> 3, lj = lane & 7;
        const int i0 = w*32 + li*8;
        float rmax[8];
        #pragma unroll
        for (int u = 0; u < 8; u++) rmax[u] = -3.0e38f;

        for (int t = 0; t < 8; t++) {
            const int j0 = t*64 + lj*8;
            u64 acc[8][4];
            #pragma unroll
            for (int jj = 0; jj < 8; jj++)
                #pragma unroll
                for (int m = 0; m < 4; m++) acc[jj][m] = 0ull;

            #pragma unroll 2
            for (int k = 0; k < 52; k += 2) {
                const ulonglong2 a00 = *(const ulonglong2*)(s_senT + k*STP + i0);
                const ulonglong2 a01 = *(const ulonglong2*)(s_senT + k*STP + i0 + 4);
                const ulonglong2 a10 = *(const ulonglong2*)(s_senT + (k+1)*STP + i0);
                const ulonglong2 a11 = *(const ulonglong2*)(s_senT + (k+1)*STP + i0 + 4);
                #pragma unroll
                for (int jj = 0; jj < 8; jj++) {
                    const float2 qf = __ldg((const float2*)(g_qpad + (j0 + jj)*QP + k));
                    const u64 b0 = pack2(qf.x, qf.x);
                    const u64 b1 = pack2(qf.y, qf.y);
                    acc[jj][0] = fma2(a00.x, b0, acc[jj][0]);
                    acc[jj][1] = fma2(a00.y, b0, acc[jj][1]);
                    acc[jj][2] = fma2(a01.x, b0, acc[jj][2]);
                    acc[jj][3] = fma2(a01.y, b0, acc[jj][3]);
                    acc[jj][0] = fma2(a10.x, b1, acc[jj][0]);
                    acc[jj][1] = fma2(a10.y, b1, acc[jj][1]);
                    acc[jj][2] = fma2(a11.x, b1, acc[jj][2]);
                    acc[jj][3] = fma2(a11.y, b1, acc[jj][3]);
                }
            }
            #pragma unroll
            for (int jj = 0; jj < 8; jj++) {
                const int j = j0 + jj;
                ulonglong2 v0; v0.x = acc[jj][0]; v0.y = acc[jj][1];
                ulonglong2 v1; v1.x = acc[jj][2]; v1.y = acc[jj][3];
                *(ulonglong2*)(Sb + (size_t)j*ND + i0)     = v0;
                *(ulonglong2*)(Sb + (size_t)j*ND + i0 + 4) = v1;
                const float2 f0 = unpack2(acc[jj][0]);
                const float2 f1 = unpack2(acc[jj][1]);
                const float2 f2 = unpack2(acc[jj][2]);
                const float2 f3 = unpack2(acc[jj][3]);
                float cm = fmaxf(fmaxf(fmaxf(f0.x, f0.y), fmaxf(f1.x, f1.y)),
                                 fmaxf(fmaxf(f2.x, f2.y), fmaxf(f3.x, f3.y)));
                atomicMax(&s_cmax[j], fenc(cm));
                rmax[0] = fmaxf(rmax[0], f0.x); rmax[1] = fmaxf(rmax[1], f0.y);
                rmax[2] = fmaxf(rmax[2], f1.x); rmax[3] = fmaxf(rmax[3], f1.y);
                rmax[4] = fmaxf(rmax[4], f2.x); rmax[5] = fmaxf(rmax[5], f2.y);
                rmax[6] = fmaxf(rmax[6], f3.x); rmax[7] = fmaxf(rmax[7], f3.y);
            }
        }
        #pragma unroll
        for (int u = 0; u < 8; u++) atomicMax(&s_rmax[i0 + u], fenc(rmax[u]));
    }
    __syncthreads();

    // ---------------- rowsum (coalesced, thread = row i) ----------------
    {
        const int i = tid;
        const float m = fdec(s_rmax[i]);
        float s0 = 0.f, s1 = 0.f, s2 = 0.f, s3 = 0.f;
        for (int j = 0; j < NQ; j += 4) {
            s0 += __expf(Sb[(size_t)(j+0)*ND + i] - m);
            s1 += __expf(Sb[(size_t)(j+1)*ND + i] - m);
            s2 += __expf(Sb[(size_t)(j+2)*ND + i] - m);
            s3 += __expf(Sb[(size_t)(j+3)*ND + i] - m);
        }
        s_rmf[i]  = m;
        s_rinv[i] = 1.0f / (s0 + s1 + s2 + s3);
    }
    __syncthreads();

    // ---------------- pass 5: T[j][k] = sum_i exp(S[j][i]-rm[i])*rinv[i]*sen[i][k] ----------------
    for (int h = 0; h < 2; h++) {
        const int j = tid + h*256;
        const float4* col4 = (const float4*)(Sb + (size_t)j*ND);
        u64 acc[26];
        #pragma unroll
        for (int c = 0; c < 26; c++) acc[c] = 0ull;

        #pragma unroll 2
        for (int i4 = 0; i4 < ND/4; i4++) {
            const float4 v4 = col4[i4];
            const float vv[4] = { v4.x, v4.y, v4.z, v4.w };
            #pragma unroll
            for (int u = 0; u < 4; u++) {
                const int i = i4*4 + u;
                const float p = __expf(vv[u] - s_rmf[i]) * s_rinv[i];
                const u64 p2 = pack2(p, p);
                const ulonglong2* srow = (const ulonglong2*)(s_sen + i*QP);
                #pragma unroll
                for (int c = 0; c < 13; c++) {
                    const ulonglong2 sv = srow[c];
                    acc[2*c+0] = fma2(sv.x, p2, acc[2*c+0]);
                    acc[2*c+1] = fma2(sv.y, p2, acc[2*c+1]);
                }
            }
        }
        ulonglong2* tdst = (ulonglong2*)(Tb + j*QP);
        #pragma unroll
        for (int c = 0; c < 13; c++) {
            ulonglong2 v; v.x = acc[2*c]; v.y = acc[2*c+1];
            tdst[c] = v;
        }
    }
    __syncthreads();

    // ---------------- colsoft: S <- exp(S-colmax)*colinv (warp per column) ----------------
    {
        const int lane = tid & 31, w = tid >> 5;
        for (int c = 0; c < 64; c++) {
            const int j = w + c*8;
            float* col = Sb + (size_t)j*ND;
            const float cm = fdec(s_cmax[j]);
            float e[8]; float s = 0.f;
            #pragma unroll
            for (int r = 0; r < 8; r++) { e[r] = __expf(col[lane + 32*r] - cm); s += e[r]; }
            #pragma unroll
            for (int o = 16; o > 0; o >>= 1) s += __shfl_xor_sync(0xffffffffu, s, o);
            const float ci = 1.0f / s;
            #pragma unroll
            for (int r = 0; r < 8; r++) col[lane + 32*r] = e[r] * ci;
        }
    }
    __syncthreads();

    // ---------------- fused pass 4+6 + epilogue ----------------
    //   aD2Q[i][k] = sum_j P[j][i]*q[j][k],  aQ2D[i][k] = sum_j P[j][i]*T[j][k]
    //   P = Sb (colinv folded). Thread: kg = tid&15 (k-quad, active<13), ig = tid>>4.
    {
        const int kg = tid & 15, ig = tid >> 4;
        if (kg < 13) {
            for (int ih = 0; ih < 2; ih++) {
                const int i0 = ig*8 + ih*128;
                u64 ac1[4][4], ac2[4][4];
                #pragma unroll
                for (int k = 0; k < 4; k++)
                    #pragma unroll
                    for (int m = 0; m < 4; m++) { ac1[k][m] = 0ull; ac2[k][m] = 0ull; }

                #pragma unroll 2
                for (int j = 0; j < NQ; j++) {
                    const ulonglong2 p01 = *(const ulonglong2*)(Sb + (size_t)j*ND + i0);
                    const ulonglong2 p23 = *(const ulonglong2*)(Sb + (size_t)j*ND + i0 + 4);
                    const u64 pa0 = p01.x, pa1 = p01.y, pa2 = p23.x, pa3 = p23.y;
                    const float4 qv = __ldg((const float4*)(g_qpad + j*QP + kg*4));
                    const float4 tv = __ldg((const float4*)(Tb + j*QP + kg*4));
                    u64 bb;
                    bb = pack2(qv.x, qv.x);
                    ac1[0][0]=fma2(pa0,bb,ac1[0][0]); ac1[0][1]=fma2(pa1,bb,ac1[0][1]);
                    ac1[0][2]=fma2(pa2,bb,ac1[0][2]); ac1[0][3]=fma2(pa3,bb,ac1[0][3]);
                    bb = pack2(qv.y, qv.y);
                    ac1[1][0]=fma2(pa0,bb,ac1[1][0]); ac1[1][1]=fma2(pa1,bb,ac1[1][1]);
                    ac1[1][2]=fma2(pa2,bb,ac1[1][2]); ac1[1][3]=fma2(pa3,bb,ac1[1][3]);
                    bb = pack2(qv.z, qv.z);
                    ac1[2][0]=fma2(pa0,bb,ac1[2][0]); ac1[2][1]=fma2(pa1,bb,ac1[2][1]);
                    ac1[2][2]=fma2(pa2,bb,ac1[2][2]); ac1[2][3]=fma2(pa3,bb,ac1[2][3]);
                    bb = pack2(qv.w, qv.w);
                    ac1[3][0]=fma2(pa0,bb,ac1[3][0]); ac1[3][1]=fma2(pa1,bb,ac1[3][1]);
                    ac1[3][2]=fma2(pa2,bb,ac1[3][2]); ac1[3][3]=fma2(pa3,bb,ac1[3][3]);
                    bb = pack2(tv.x, tv.x);
                    ac2[0][0]=fma2(pa0,bb,ac2[0][0]); ac2[0][1]=fma2(pa1,bb,ac2[0][1]);
                    ac2[0][2]=fma2(pa2,bb,ac2[0][2]); ac2[0][3]=fma2(pa3,bb,ac2[0][3]);
                    bb = pack2(tv.y, tv.y);
                    ac2[1][0]=fma2(pa0,bb,ac2[1][0]); ac2[1][1]=fma2(pa1,bb,ac2[1][1]);
                    ac2[1][2]=fma2(pa2,bb,ac2[1][2]); ac2[1][3]=fma2(pa3,bb,ac2[1][3]);
                    bb = pack2(tv.z, tv.z);
                    ac2[2][0]=fma2(pa0,bb,ac2[2][0]); ac2[2][1]=fma2(pa1,bb,ac2[2][1]);
                    ac2[2][2]=fma2(pa2,bb,ac2[2][2]); ac2[2][3]=fma2(pa3,bb,ac2[2][3]);
                    bb = pack2(tv.w, tv.w);
                    ac2[3][0]=fma2(pa0,bb,ac2[3][0]); ac2[3][1]=fma2(pa1,bb,ac2[3][1]);
                    ac2[3][2]=fma2(pa2,bb,ac2[3][2]); ac2[3][3]=fma2(pa3,bb,ac2[3][3]);
                }

                // epilogue for this i-half
                #pragma unroll
                for (int m = 0; m < 4; m++) {
                    float2 u1[4], u2[4];
                    #pragma unroll
                    for (int k = 0; k < 4; k++) { u1[k] = unpack2(ac1[k][m]); u2[k] = unpack2(ac2[k][m]); }
                    #pragma unroll
                    for (int par = 0; par < 2; par++) {
                        const int i = i0 + 2*m + par;
                        float a1v[4], a2v[4];
                        #pragma unroll
                        for (int k = 0; k < 4; k++) {
                            a1v[k] = par ? u1[k].y : u1[k].x;
                            a2v[k] = par ? u2[k].y : u2[k].x;
                        }
                        const float4 sv = *(const float4*)(s_sen + i*QP + kg*4);
                        float* orow = out + ((size_t)b*ND + i) * NOUT;
                        if (kg < 12) {
                            *(float4*)(orow + kg*4) = sv;
                            *(float2*)(orow +  50 + kg*4) = make_float2(a1v[0], a1v[1]);
                            *(float2*)(orow +  52 + kg*4) = make_float2(a1v[2], a1v[3]);
                            float4 p2; p2.x = sv.x*a1v[0]; p2.y = sv.y*a1v[1];
                                       p2.z = sv.z*a1v[2]; p2.w = sv.w*a1v[3];
                            *(float4*)(orow + 100 + kg*4) = p2;
                            *(float2*)(orow + 150 + kg*4) = make_float2(sv.x*a2v[0], sv.y*a2v[1]);
                            *(float2*)(orow + 152 + kg*4) = make_float2(sv.z*a2v[2], sv.w*a2v[3]);
                        } else {
                            *(float2*)(orow +  48) = make_float2(sv.x, sv.y);
                            *(float2*)(orow +  98) = make_float2(a1v[0], a1v[1]);
                            *(float2*)(orow + 148) = make_float2(sv.x*a1v[0], sv.y*a1v[1]);
                            *(float2*)(orow + 198) = make_float2(sv.x*a2v[0], sv.y*a2v[1]);
                        }
                    }
                }
            }
        }
    }
}

// ================= launch =================
extern "C" void kernel_launch(void* const* d_in, const int* in_sizes, int n_in,
                              void* d_out, int out_size)
{
    const float* query = nullptr;
    const float* doc   = nullptr;
    const float* Wp    = nullptr;
    for (int i = 0; i < n_in; i++) {
        if      (in_sizes[i] == 150)     Wp    = (const float*)d_in[i];
        else if (in_sizes[i] == NQ*NF)   query = (const float*)d_in[i];
        else                             doc   = (const float*)d_in[i];
    }

    static bool attr_done = false;
    if (!attr_done) {
        cudaFuncSetAttribute(cross_attn_main,
                             cudaFuncAttributeMaxDynamicSharedMemorySize, SMEM_BYTES);
        attr_done = true;
    }

    k_prep<<<2, 256>>>(query, Wp);
    cross_attn_main<<<512, 256, SMEM_BYTES>>>(doc, Wp, (float*)d_out);
}

// round 8
// speedup vs baseline: 1.7579x; 1.4139x over previous
#include <cuda_runtime.h>

#define NQ 512
#define ND 256
#define NF 50
#define QP 52
#define STP 260
#define NOUT 200

typedef unsigned long long u64;
typedef unsigned int u32;

// ---------------- global scratch (no allocations) ----------------
__device__ float g_S   [67108864];  // [b][j][i] S col-major; later P = exp(S-cmax)*cinv in place
__device__ float g_T   [13631488];  // [b][j][52]
__device__ float g_qpad[26624];     // [512][52]: cols0..49 q, col50=1, col51=qterm

// ---------------- helpers ----------------
__device__ __forceinline__ u64 pack2(float x, float y) {
    u64 r; asm("mov.b64 %0, {%1, %2};" : "=l"(r) : "f"(x), "f"(y)); return r;
}
__device__ __forceinline__ u64 fma2(u64 a, u64 b, u64 c) {
    u64 d; asm("fma.rn.f32x2 %0, %1, %2, %3;" : "=l"(d) : "l"(a), "l"(b), "l"(c)); return d;
}
__device__ __forceinline__ float2 unpack2(u64 v) {
    float lo, hi; asm("mov.b64 {%0, %1}, %2;" : "=f"(lo), "=f"(hi) : "l"(v));
    return make_float2(lo, hi);
}
__device__ __forceinline__ u32 fenc(float f) {
    u32 u = __float_as_uint(f);
    return (u & 0x80000000u) ? ~u : (u | 0x80000000u);
}
__device__ __forceinline__ float fdec(u32 e) {
    return __uint_as_float((e & 0x80000000u) ? (e & 0x7FFFFFFFu) : ~e);
}

// ================= K_prep: padded q with qterm fold =================
__global__ __launch_bounds__(256)
void k_prep(const float* __restrict__ q, const float* __restrict__ W)
{
    const int j = blockIdx.x * 256 + threadIdx.x;
    float qr[NF];
    #pragma unroll
    for (int k = 0; k < NF; k++) qr[k] = __ldg(q + j*NF + k);
    float a = 0.f;
    #pragma unroll
    for (int k = 0; k < NF; k++) a += qr[k] * __ldg(W + 50 + k);
    float* dst = g_qpad + j*QP;
    #pragma unroll
    for (int k = 0; k < NF; k++) dst[k] = qr[k];
    dst[50] = 1.0f; dst[51] = a;
}

// ================= main monolith: 512 threads =================
// SMEM: s_q 26624 | s_sen 13312 | s_senT 13520 (aliased: 2 P-tiles 2*4096) |
//       s_w 152 | s_cmax 512 | s_rmaxu 256 | s_rmf 256 | s_rinv 256 | s_red 512
#define SMEM_FLOATS (26624 + 13312 + 13520 + 152 + 512 + 256 + 256 + 256 + 512)
#define SMEM_BYTES  (SMEM_FLOATS * 4)

__global__ __launch_bounds__(512, 1)
void cross_attn_main(const float* __restrict__ doc, const float* __restrict__ W,
                     float* __restrict__ out)
{
    extern __shared__ float sm[];
    float* s_q     = sm;                       // [512][QP]
    float* s_sen   = s_q + 26624;              // [256][QP]
    float* s_senT  = s_sen + 13312;            // [52][STP] phase1; later 2 tiles [16][256]
    float* s_w     = s_senT + 13520;           // [152]
    float* s_cmax  = s_w + 152;                // [512] (plain float)
    u32*   s_rmaxu = (u32*)(s_cmax + 512);     // [256]
    float* s_rmf   = (float*)(s_rmaxu + 256);  // [256]
    float* s_rinv  = s_rmf + 256;              // [256]
    float* s_red   = s_rinv + 256;             // [512]
    float* tile0   = s_senT;                   // [16][256]
    float* tile1   = s_senT + 4096;            // [16][256]

    const int tid = threadIdx.x;               // 0..511
    const int b   = blockIdx.x;
    float* Sb = g_S + (size_t)b * NQ * ND;
    float* Tb = g_T + (size_t)b * NQ * QP;

    // ---------------- load phase ----------------
    if (tid < 150) s_w[tid] = __ldg(W + tid);
    // q from prepped padded copy (13 float4 per row)
    for (int x = tid; x < 512*13; x += 512) {
        const int j = x / 13, c = x - j*13;
        *(float4*)(s_q + j*QP + c*4) = __ldg((const float4*)(g_qpad + j*QP + c*4));
    }
    for (int idx = tid; idx < ND*NF; idx += 512) {
        const int i = idx / NF, k = idx - i*NF;
        s_sen[i*QP + k] = doc[(size_t)b*ND*NF + idx];
    }
    if (tid < 256) { s_sen[tid*QP + 50] = 0.f; s_sen[tid*QP + 51] = 0.f; s_rmaxu[tid] = 0u; }
    __syncthreads();

    // senT rows 0..49 (w3-folded); row50 = senw1; row51 = ones
    for (int idx = tid; idx < 50*256; idx += 512) {
        const int k = idx >> 8, i = idx & 255;
        s_senT[k*STP + i] = s_sen[i*QP + k] * s_w[100 + k];
    }
    if (tid < 256) {
        const int i = tid;
        float a = 0.f;
        #pragma unroll
        for (int k = 0; k < NF; k++) a += s_sen[i*QP + k] * s_w[k];
        s_senT[50*STP + i] = a;
        s_senT[51*STP + i] = 1.0f;
    }
    __syncthreads();

    // ---------------- pass 1: S[j][i] = sum_{k=0..51} senT[k][i]*q[j][k] + fused maxes ----
    // lanes = tx (i), warp = ty (j). Each warp covers ALL 256 i for its j's -> colmax by shuffle.
    {
        const int tx = tid & 31, ty = tid >> 5;   // warp id = ty
        const int i0 = tx * 8;
        float rmax[8];
        #pragma unroll
        for (int u = 0; u < 8; u++) rmax[u] = -3.0e38f;

        for (int jc = 0; jc < 4; jc++) {
            u64 acc[8][4];
            #pragma unroll
            for (int jj = 0; jj < 8; jj++)
                #pragma unroll
                for (int m = 0; m < 4; m++) acc[jj][m] = 0ull;

            #pragma unroll 2
            for (int k = 0; k < 52; k += 2) {
                const ulonglong2 a00 = *(const ulonglong2*)(s_senT + k*STP + i0);
                const ulonglong2 a01 = *(const ulonglong2*)(s_senT + k*STP + i0 + 4);
                const ulonglong2 a10 = *(const ulonglong2*)(s_senT + (k+1)*STP + i0);
                const ulonglong2 a11 = *(const ulonglong2*)(s_senT + (k+1)*STP + i0 + 4);
                #pragma unroll
                for (int jj = 0; jj < 8; jj++) {
                    const int j = jc*128 + jj*16 + ty;
                    const float2 qf = *(const float2*)(s_q + j*QP + k);
                    const u64 b0 = pack2(qf.x, qf.x);
                    const u64 b1 = pack2(qf.y, qf.y);
                    acc[jj][0] = fma2(a00.x, b0, acc[jj][0]);
                    acc[jj][1] = fma2(a00.y, b0, acc[jj][1]);
                    acc[jj][2] = fma2(a01.x, b0, acc[jj][2]);
                    acc[jj][3] = fma2(a01.y, b0, acc[jj][3]);
                    acc[jj][0] = fma2(a10.x, b1, acc[jj][0]);
                    acc[jj][1] = fma2(a10.y, b1, acc[jj][1]);
                    acc[jj][2] = fma2(a11.x, b1, acc[jj][2]);
                    acc[jj][3] = fma2(a11.y, b1, acc[jj][3]);
                }
            }
            #pragma unroll
            for (int jj = 0; jj < 8; jj++) {
                const int j = jc*128 + jj*16 + ty;
                ulonglong2 v0; v0.x = acc[jj][0]; v0.y = acc[jj][1];
                ulonglong2 v1; v1.x = acc[jj][2]; v1.y = acc[jj][3];
                *(ulonglong2*)(Sb + (size_t)j*ND + i0)     = v0;
                *(ulonglong2*)(Sb + (size_t)j*ND + i0 + 4) = v1;
                const float2 f0 = unpack2(acc[jj][0]);
                const float2 f1 = unpack2(acc[jj][1]);
                const float2 f2 = unpack2(acc[jj][2]);
                const float2 f3 = unpack2(acc[jj][3]);
                // colmax: warp spans all 256 i for this j -> full shuffle reduce
                float cm = fmaxf(fmaxf(fmaxf(f0.x, f0.y), fmaxf(f1.x, f1.y)),
                                 fmaxf(fmaxf(f2.x, f2.y), fmaxf(f3.x, f3.y)));
                #pragma unroll
                for (int o = 16; o > 0; o >>= 1)
                    cm = fmaxf(cm, __shfl_xor_sync(0xffffffffu, cm, o));
                if (tx == 0) s_cmax[j] = cm;
                // rowmax running
                rmax[0] = fmaxf(rmax[0], f0.x); rmax[1] = fmaxf(rmax[1], f0.y);
                rmax[2] = fmaxf(rmax[2], f1.x); rmax[3] = fmaxf(rmax[3], f1.y);
                rmax[4] = fmaxf(rmax[4], f2.x); rmax[5] = fmaxf(rmax[5], f2.y);
                rmax[6] = fmaxf(rmax[6], f3.x); rmax[7] = fmaxf(rmax[7], f3.y);
            }
        }
        #pragma unroll
        for (int u = 0; u < 8; u++) atomicMax(&s_rmaxu[i0 + u], fenc(rmax[u]));
    }
    __syncthreads();

    // ---------------- rowsum: one coalesced S sweep (2 threads per row) ----------------
    {
        const int i = tid & 255, h = tid >> 8;
        const float m = fdec(s_rmaxu[i]);
        float s0 = 0.f, s1 = 0.f;
        for (int j = h*256; j < h*256 + 256; j += 2) {
            s0 += __expf(Sb[(size_t)(j+0)*ND + i] - m);
            s1 += __expf(Sb[(size_t)(j+1)*ND + i] - m);
        }
        s_red[tid] = s0 + s1;
        if (h == 0) s_rmf[i] = m;
    }
    __syncthreads();
    if (tid < 256) s_rinv[tid] = 1.0f / (s_red[tid] + s_red[tid + 256]);
    __syncthreads();

    // ---------------- pass 5: T[j][k] = sum_i exp(S[j][i]-rm[i])*rinv[i]*sen[i][k] --------
    // thread = column j; per-thread contiguous float4 column reads, exp on the fly
    {
        const int j = tid;
        const float4* col4 = (const float4*)(Sb + (size_t)j*ND);
        u64 acc[26];
        #pragma unroll
        for (int c = 0; c < 26; c++) acc[c] = 0ull;

        #pragma unroll 2
        for (int i4 = 0; i4 < ND/4; i4++) {
            const float4 v4 = col4[i4];
            const float vv[4] = { v4.x, v4.y, v4.z, v4.w };
            #pragma unroll
            for (int u = 0; u < 4; u++) {
                const int i = i4*4 + u;
                const float p = __expf(vv[u] - s_rmf[i]) * s_rinv[i];
                const u64 p2 = pack2(p, p);
                const ulonglong2* srow = (const ulonglong2*)(s_sen + i*QP);
                #pragma unroll
                for (int c = 0; c < 13; c++) {
                    const ulonglong2 sv = srow[c];
                    acc[2*c+0] = fma2(sv.x, p2, acc[2*c+0]);
                    acc[2*c+1] = fma2(sv.y, p2, acc[2*c+1]);
                }
            }
        }
        ulonglong2* tdst = (ulonglong2*)(Tb + j*QP);
        #pragma unroll
        for (int c = 0; c < 13; c++) {
            ulonglong2 v; v.x = acc[2*c]; v.y = acc[2*c+1];
            tdst[c] = v;
        }
    }
    __syncthreads();

    // ---------------- colsoft: S <- exp(S-cmax)*cinv (warp per column, cinv folded) -------
    {
        const int lane = tid & 31, w = tid >> 5;   // 16 warps
        for (int c = 0; c < 32; c++) {
            const int j = w + c*16;
            float* col = Sb + (size_t)j*ND;
            const float cm = s_cmax[j];
            float e[8]; float s = 0.f;
            #pragma unroll
            for (int r = 0; r < 8; r++) { e[r] = __expf(col[lane + 32*r] - cm); s += e[r]; }
            #pragma unroll
            for (int o = 16; o > 0; o >>= 1) s += __shfl_xor_sync(0xffffffffu, s, o);
            const float ci = 1.0f / s;
            #pragma unroll
            for (int r = 0; r < 8; r++) col[lane + 32*r] = e[r] * ci;
        }
    }
    __syncthreads();

    // ---------------- fused pass 4+6: double-buffered staged-P GEMM + epilogue ------------
    //   aD2Q[i][k] = sum_j P[j][i]*q[j][k],  aQ2D[i][k] = sum_j P[j][i]*T[j][k]
    //   P = Sb (cinv folded). Chunks of 16 j staged into alternating SMEM tiles.
    {
        const int kg = tid & 15, ig = tid >> 4;    // k-quad (active<13), i-group
        const int i0 = ig * 8;
        u64 ac1[4][4], ac2[4][4];
        #pragma unroll
        for (int k = 0; k < 4; k++)
            #pragma unroll
            for (int m = 0; m < 4; m++) { ac1[k][m] = 0ull; ac2[k][m] = 0ull; }

        // stage chunk 0
        #pragma unroll
        for (int t = 0; t < 8; t++) {
            const int e = t*512 + tid;
            const int jl = e >> 8, i = e & 255;
            tile0[jl*256 + i] = Sb[(size_t)jl*ND + i];
        }
        __syncthreads();

        for (int jc = 0; jc < 32; jc++) {
            float* cur = (jc & 1) ? tile1 : tile0;
            float* nxt = (jc & 1) ? tile0 : tile1;

            // prefetch next chunk into registers (overlaps with compute below)
            float pre[8];
            if (jc < 31) {
                #pragma unroll
                for (int t = 0; t < 8; t++) {
                    const int e = t*512 + tid;
                    const int jl = e >> 8, i = e & 255;
                    pre[t] = Sb[(size_t)((jc+1)*16 + jl)*ND + i];
                }
            }

            if (kg < 13) {
                #pragma unroll 2
                for (int jj = 0; jj < 16; jj++) {
                    const int j = jc*16 + jj;
                    const ulonglong2 p01 = *(const ulonglong2*)(cur + jj*256 + i0);
                    const ulonglong2 p23 = *(const ulonglong2*)(cur + jj*256 + i0 + 4);
                    const u64 pa0 = p01.x, pa1 = p01.y, pa2 = p23.x, pa3 = p23.y;
                    const float4 qv = *(const float4*)(s_q + j*QP + kg*4);
                    const float4 tv = __ldg((const float4*)(Tb + j*QP + kg*4));
                    u64 bb;
                    bb = pack2(qv.x, qv.x);
                    ac1[0][0]=fma2(pa0,bb,ac1[0][0]); ac1[0][1]=fma2(pa1,bb,ac1[0][1]);
                    ac1[0][2]=fma2(pa2,bb,ac1[0][2]); ac1[0][3]=fma2(pa3,bb,ac1[0][3]);
                    bb = pack2(qv.y, qv.y);
                    ac1[1][0]=fma2(pa0,bb,ac1[1][0]); ac1[1][1]=fma2(pa1,bb,ac1[1][1]);
                    ac1[1][2]=fma2(pa2,bb,ac1[1][2]); ac1[1][3]=fma2(pa3,bb,ac1[1][3]);
                    bb = pack2(qv.z, qv.z);
                    ac1[2][0]=fma2(pa0,bb,ac1[2][0]); ac1[2][1]=fma2(pa1,bb,ac1[2][1]);
                    ac1[2][2]=fma2(pa2,bb,ac1[2][2]); ac1[2][3]=fma2(pa3,bb,ac1[2][3]);
                    bb = pack2(qv.w, qv.w);
                    ac1[3][0]=fma2(pa0,bb,ac1[3][0]); ac1[3][1]=fma2(pa1,bb,ac1[3][1]);
                    ac1[3][2]=fma2(pa2,bb,ac1[3][2]); ac1[3][3]=fma2(pa3,bb,ac1[3][3]);
                    bb = pack2(tv.x, tv.x);
                    ac2[0][0]=fma2(pa0,bb,ac2[0][0]); ac2[0][1]=fma2(pa1,bb,ac2[0][1]);
                    ac2[0][2]=fma2(pa2,bb,ac2[0][2]); ac2[0][3]=fma2(pa3,bb,ac2[0][3]);
                    bb = pack2(tv.y, tv.y);
                    ac2[1][0]=fma2(pa0,bb,ac2[1][0]); ac2[1][1]=fma2(pa1,bb,ac2[1][1]);
                    ac2[1][2]=fma2(pa2,bb,ac2[1][2]); ac2[1][3]=fma2(pa3,bb,ac2[1][3]);
                    bb = pack2(tv.z, tv.z);
                    ac2[2][0]=fma2(pa0,bb,ac2[2][0]); ac2[2][1]=fma2(pa1,bb,ac2[2][1]);
                    ac2[2][2]=fma2(pa2,bb,ac2[2][2]); ac2[2][3]=fma2(pa3,bb,ac2[2][3]);
                    bb = pack2(tv.w, tv.w);
                    ac2[3][0]=fma2(pa0,bb,ac2[3][0]); ac2[3][1]=fma2(pa1,bb,ac2[3][1]);
                    ac2[3][2]=fma2(pa2,bb,ac2[3][2]); ac2[3][3]=fma2(pa3,bb,ac2[3][3]);
                }
            }

            if (jc < 31) {
                #pragma unroll
                for (int t = 0; t < 8; t++) {
                    const int e = t*512 + tid;
                    const int jl = e >> 8, i = e & 255;
                    nxt[jl*256 + i] = pre[t];
                }
            }
            __syncthreads();
        }

        // ---------------- epilogue: [sen | aD2Q | sen*aD2Q | sen*aQ2D] ----------------
        if (kg < 13) {
            #pragma unroll
            for (int m = 0; m < 4; m++) {
                float2 u1[4], u2[4];
                #pragma unroll
                for (int k = 0; k < 4; k++) { u1[k] = unpack2(ac1[k][m]); u2[k] = unpack2(ac2[k][m]); }
                #pragma unroll
                for (int par = 0; par < 2; par++) {
                    const int i = i0 + 2*m + par;
                    float a1v[4], a2v[4];
                    #pragma unroll
                    for (int k = 0; k < 4; k++) {
                        a1v[k] = par ? u1[k].y : u1[k].x;
                        a2v[k] = par ? u2[k].y : u2[k].x;
                    }
                    const float4 sv = *(const float4*)(s_sen + i*QP + kg*4);
                    float* orow = out + ((size_t)b*ND + i) * NOUT;
                    if (kg < 12) {
                        *(float4*)(orow + kg*4) = sv;
                        *(float2*)(orow +  50 + kg*4) = make_float2(a1v[0], a1v[1]);
                        *(float2*)(orow +  52 + kg*4) = make_float2(a1v[2], a1v[3]);
                        float4 p2; p2.x = sv.x*a1v[0]; p2.y = sv.y*a1v[1];
                                   p2.z = sv.z*a1v[2]; p2.w = sv.w*a1v[3];
                        *(float4*)(orow + 100 + kg*4) = p2;
                        *(float2*)(orow + 150 + kg*4) = make_float2(sv.x*a2v[0], sv.y*a2v[1]);
                        *(float2*)(orow + 152 + kg*4) = make_float2(sv.z*a2v[2], sv.w*a2v[3]);
                    } else {
                        *(float2*)(orow +  48) = make_float2(sv.x, sv.y);
                        *(float2*)(orow +  98) = make_float2(a1v[0], a1v[1]);
                        *(float2*)(orow + 148) = make_float2(sv.x*a1v[0], sv.y*a1v[1]);
                        *(float2*)(orow + 198) = make_float2(sv.x*a2v[0], sv.y*a2v[1]);
                    }
                }
            }
        }
    }
}

// ================= launch =================
extern "C" void kernel_launch(void* const* d_in, const int* in_sizes, int n_in,
                              void* d_out, int out_size)
{
    const float* query = nullptr;
    const float* doc   = nullptr;
    const float* Wp    = nullptr;
    for (int i = 0; i < n_in; i++) {
        if      (in_sizes[i] == 150)     Wp    = (const float*)d_in[i];
        else if (in_sizes[i] == NQ*NF)   query = (const float*)d_in[i];
        else                             doc   = (const float*)d_in[i];
    }

    static bool attr_done = false;
    if (!attr_done) {
        cudaFuncSetAttribute(cross_attn_main,
                             cudaFuncAttributeMaxDynamicSharedMemorySize, SMEM_BYTES);
        attr_done = true;
    }

    k_prep<<<2, 256>>>(query, Wp);
    cross_attn_main<<<512, 512, SMEM_BYTES>>>(doc, Wp, (float*)d_out);
}

// round 9
// speedup vs baseline: 1.8289x; 1.0404x over previous
#include <cuda_runtime.h>

#define NQ 512
#define ND 256
#define NF 50
#define QP 52
#define STP 260
#define NOUT 200
#define L2E 1.44269504088896341f

typedef unsigned long long u64;
typedef unsigned int u32;

// ---------------- global scratch (no allocations) ----------------
__device__ float g_S   [67108864];  // [b][j][i] S col-major (log2-scaled logits)
__device__ float g_T   [13631488];  // [b][j][52]
__device__ float g_qpad[26624];     // [512][52]: cols0..49 q, col50=1, col51=qterm*L2E

// ---------------- helpers ----------------
__device__ __forceinline__ u64 pack2(float x, float y) {
    u64 r; asm("mov.b64 %0, {%1, %2};" : "=l"(r) : "f"(x), "f"(y)); return r;
}
__device__ __forceinline__ u64 fma2(u64 a, u64 b, u64 c) {
    u64 d; asm("fma.rn.f32x2 %0, %1, %2, %3;" : "=l"(d) : "l"(a), "l"(b), "l"(c)); return d;
}
__device__ __forceinline__ float2 unpack2(u64 v) {
    float lo, hi; asm("mov.b64 {%0, %1}, %2;" : "=f"(lo), "=f"(hi) : "l"(v));
    return make_float2(lo, hi);
}
__device__ __forceinline__ float ex2(float x) {
    float y; asm("ex2.approx.ftz.f32 %0, %1;" : "=f"(y) : "f"(x)); return y;
}
__device__ __forceinline__ u32 fenc(float f) {
    u32 u = __float_as_uint(f);
    return (u & 0x80000000u) ? ~u : (u | 0x80000000u);
}
__device__ __forceinline__ float fdec(u32 e) {
    return __uint_as_float((e & 0x80000000u) ? (e & 0x7FFFFFFFu) : ~e);
}

// ================= K_prep: padded q with (log2e-scaled) qterm fold =================
__global__ __launch_bounds__(256)
void k_prep(const float* __restrict__ q, const float* __restrict__ W)
{
    const int j = blockIdx.x * 256 + threadIdx.x;
    float qr[NF];
    #pragma unroll
    for (int k = 0; k < NF; k++) qr[k] = __ldg(q + j*NF + k);
    float a = 0.f;
    #pragma unroll
    for (int k = 0; k < NF; k++) a += qr[k] * __ldg(W + 50 + k);
    float* dst = g_qpad + j*QP;
    #pragma unroll
    for (int k = 0; k < NF; k++) dst[k] = qr[k];
    dst[50] = 1.0f; dst[51] = a * L2E;
}

// ================= main monolith: 512 threads =================
#define SMEM_FLOATS (26624 + 13312 + 13520 + 152 + 512 + 512 + 256 + 256 + 256)
#define SMEM_BYTES  (SMEM_FLOATS * 4)

__global__ __launch_bounds__(512, 1)
void cross_attn_main(const float* __restrict__ doc, const float* __restrict__ W,
                     float* __restrict__ out)
{
    extern __shared__ float sm[];
    float* s_q     = sm;                       // [512][QP]
    float* s_sen   = s_q + 26624;              // [256][QP]
    float* s_senT  = s_sen + 13312;            // [52][STP]; later s_red[16][256] / 2 P-tiles
    float* s_w     = s_senT + 13520;           // [152]  (pre-scaled by log2e)
    float* s_cmax  = s_w + 152;                // [512]
    float* s_cinv  = s_cmax + 512;             // [512]
    u32*   s_rmaxu = (u32*)(s_cinv + 512);     // [256]
    float* s_rmf   = (float*)(s_rmaxu + 256);  // [256]
    float* s_rinv  = s_rmf + 256;              // [256]
    float* s_red   = s_senT;                   // [16][256] alias
    float* tile0   = s_senT;                   // [16][256] alias
    float* tile1   = s_senT + 4096;            // [16][256] alias

    const int tid = threadIdx.x;               // 0..511
    const int b   = blockIdx.x;
    float* Sb = g_S + (size_t)b * NQ * ND;
    float* Tb = g_T + (size_t)b * NQ * QP;

    // ---------------- load phase ----------------
    if (tid < 150) s_w[tid] = __ldg(W + tid) * L2E;
    for (int x = tid; x < 512*13; x += 512) {
        const int j = x / 13, c = x - j*13;
        *(float4*)(s_q + j*QP + c*4) = __ldg((const float4*)(g_qpad + j*QP + c*4));
    }
    for (int idx = tid; idx < ND*NF; idx += 512) {
        const int i = idx / NF, k = idx - i*NF;
        s_sen[i*QP + k] = doc[(size_t)b*ND*NF + idx];
    }
    if (tid < 256) { s_sen[tid*QP + 50] = 0.f; s_sen[tid*QP + 51] = 0.f; s_rmaxu[tid] = 0u; }
    __syncthreads();

    // senT rows 0..49 (w3*log2e folded); row50 = senw1*log2e; row51 = ones
    for (int idx = tid; idx < 50*256; idx += 512) {
        const int k = idx >> 8, i = idx & 255;
        s_senT[k*STP + i] = s_sen[i*QP + k] * s_w[100 + k];
    }
    if (tid < 256) {
        const int i = tid;
        float a = 0.f;
        #pragma unroll
        for (int k = 0; k < NF; k++) a += s_sen[i*QP + k] * s_w[k];
        s_senT[50*STP + i] = a;
        s_senT[51*STP + i] = 1.0f;
    }
    __syncthreads();

    // ---------------- pass 1: S' = log2e * S  GEMM + fused row/col max ----------------
    {
        const int tx = tid & 31, ty = tid >> 5;
        const int i0 = tx * 8;
        float rmax[8];
        #pragma unroll
        for (int u = 0; u < 8; u++) rmax[u] = -3.0e38f;

        for (int jc = 0; jc < 4; jc++) {
            u64 acc[8][4];
            #pragma unroll
            for (int jj = 0; jj < 8; jj++)
                #pragma unroll
                for (int m = 0; m < 4; m++) acc[jj][m] = 0ull;

            #pragma unroll 2
            for (int k = 0; k < 52; k += 2) {
                const ulonglong2 a00 = *(const ulonglong2*)(s_senT + k*STP + i0);
                const ulonglong2 a01 = *(const ulonglong2*)(s_senT + k*STP + i0 + 4);
                const ulonglong2 a10 = *(const ulonglong2*)(s_senT + (k+1)*STP + i0);
                const ulonglong2 a11 = *(const ulonglong2*)(s_senT + (k+1)*STP + i0 + 4);
                #pragma unroll
                for (int jj = 0; jj < 8; jj++) {
                    const int j = jc*128 + jj*16 + ty;
                    const float2 qf = *(const float2*)(s_q + j*QP + k);
                    const u64 b0 = pack2(qf.x, qf.x);
                    const u64 b1 = pack2(qf.y, qf.y);
                    acc[jj][0] = fma2(a00.x, b0, acc[jj][0]);
                    acc[jj][1] = fma2(a00.y, b0, acc[jj][1]);
                    acc[jj][2] = fma2(a01.x, b0, acc[jj][2]);
                    acc[jj][3] = fma2(a01.y, b0, acc[jj][3]);
                    acc[jj][0] = fma2(a10.x, b1, acc[jj][0]);
                    acc[jj][1] = fma2(a10.y, b1, acc[jj][1]);
                    acc[jj][2] = fma2(a11.x, b1, acc[jj][2]);
                    acc[jj][3] = fma2(a11.y, b1, acc[jj][3]);
                }
            }
            #pragma unroll
            for (int jj = 0; jj < 8; jj++) {
                const int j = jc*128 + jj*16 + ty;
                ulonglong2 v0; v0.x = acc[jj][0]; v0.y = acc[jj][1];
                ulonglong2 v1; v1.x = acc[jj][2]; v1.y = acc[jj][3];
                *(ulonglong2*)(Sb + (size_t)j*ND + i0)     = v0;
                *(ulonglong2*)(Sb + (size_t)j*ND + i0 + 4) = v1;
                const float2 f0 = unpack2(acc[jj][0]);
                const float2 f1 = unpack2(acc[jj][1]);
                const float2 f2 = unpack2(acc[jj][2]);
                const float2 f3 = unpack2(acc[jj][3]);
                float cm = fmaxf(fmaxf(fmaxf(f0.x, f0.y), fmaxf(f1.x, f1.y)),
                                 fmaxf(fmaxf(f2.x, f2.y), fmaxf(f3.x, f3.y)));
                #pragma unroll
                for (int o = 16; o > 0; o >>= 1)
                    cm = fmaxf(cm, __shfl_xor_sync(0xffffffffu, cm, o));
                if (tx == 0) s_cmax[j] = cm;
                rmax[0] = fmaxf(rmax[0], f0.x); rmax[1] = fmaxf(rmax[1], f0.y);
                rmax[2] = fmaxf(rmax[2], f1.x); rmax[3] = fmaxf(rmax[3], f1.y);
                rmax[4] = fmaxf(rmax[4], f2.x); rmax[5] = fmaxf(rmax[5], f2.y);
                rmax[6] = fmaxf(rmax[6], f3.x); rmax[7] = fmaxf(rmax[7], f3.y);
            }
        }
        #pragma unroll
        for (int u = 0; u < 8; u++) atomicMax(&s_rmaxu[i0 + u], fenc(rmax[u]));
    }
    __syncthreads();

    // ---------------- stats sweep: ONE read of S -> cinv[j] AND rinv[i] ----------------
    {
        const int lane = tid & 31, w = tid >> 5;
        float rm[8], racc[8];
        #pragma unroll
        for (int r = 0; r < 8; r++) { rm[r] = fdec(s_rmaxu[lane + 32*r]); racc[r] = 0.f; }
        if (w == 0) {
            #pragma unroll
            for (int r = 0; r < 8; r++) s_rmf[lane + 32*r] = rm[r];
        }
        for (int c = 0; c < 32; c++) {
            const int j = w + c*16;
            const float* col = Sb + (size_t)j*ND;
            const float cm = s_cmax[j];
            float s = 0.f;
            #pragma unroll
            for (int r = 0; r < 8; r++) {
                const float v = col[lane + 32*r];
                s       += ex2(v - cm);
                racc[r] += ex2(v - rm[r]);
            }
            #pragma unroll
            for (int o = 16; o > 0; o >>= 1) s += __shfl_xor_sync(0xffffffffu, s, o);
            if (lane == 0) s_cinv[j] = 1.0f / s;
        }
        #pragma unroll
        for (int r = 0; r < 8; r++) s_red[w*256 + lane + 32*r] = racc[r];
    }
    __syncthreads();
    if (tid < 256) {
        float s = 0.f;
        #pragma unroll
        for (int w = 0; w < 16; w++) s += s_red[w*256 + tid];
        s_rinv[tid] = 1.0f / s;
    }
    __syncthreads();

    // ---------------- pass 5: T[j][k] = sum_i ex2(S[j][i]-rm[i])*rinv[i]*sen[i][k] ------
    {
        const int j = tid;
        const float4* col4 = (const float4*)(Sb + (size_t)j*ND);
        u64 acc[26];
        #pragma unroll
        for (int c = 0; c < 26; c++) acc[c] = 0ull;

        #pragma unroll 2
        for (int i4 = 0; i4 < ND/4; i4++) {
            const float4 v4 = col4[i4];
            const float vv[4] = { v4.x, v4.y, v4.z, v4.w };
            #pragma unroll
            for (int u = 0; u < 4; u++) {
                const int i = i4*4 + u;
                const float p = ex2(vv[u] - s_rmf[i]) * s_rinv[i];
                const u64 p2 = pack2(p, p);
                const ulonglong2* srow = (const ulonglong2*)(s_sen + i*QP);
                #pragma unroll
                for (int c = 0; c < 13; c++) {
                    const ulonglong2 sv = srow[c];
                    acc[2*c+0] = fma2(sv.x, p2, acc[2*c+0]);
                    acc[2*c+1] = fma2(sv.y, p2, acc[2*c+1]);
                }
            }
        }
        ulonglong2* tdst = (ulonglong2*)(Tb + j*QP);
        #pragma unroll
        for (int c = 0; c < 13; c++) {
            ulonglong2 v; v.x = acc[2*c]; v.y = acc[2*c+1];
            tdst[c] = v;
        }
    }
    __syncthreads();

    // ---------------- fused pass 4+6: staging computes P on the fly ------------
    //   P[j][i] = ex2(S[j][i]-cmax[j]) * cinv[j]
    //   aD2Q[i][k] = sum_j P[j][i]*q[j][k],  aQ2D[i][k] = sum_j P[j][i]*T[j][k]
    {
        const int kg = tid & 15, ig = tid >> 4;
        const int i0 = ig * 8;
        u64 ac1[4][4], ac2[4][4];
        #pragma unroll
        for (int k = 0; k < 4; k++)
            #pragma unroll
            for (int m = 0; m < 4; m++) { ac1[k][m] = 0ull; ac2[k][m] = 0ull; }

        // stage chunk 0 (exp transform at stage time)
        #pragma unroll
        for (int t = 0; t < 8; t++) {
            const int e = t*512 + tid;
            const int jl = e >> 8, i = e & 255;
            const float v = Sb[(size_t)jl*ND + i];
            tile0[jl*256 + i] = ex2(v - s_cmax[jl]) * s_cinv[jl];
        }
        __syncthreads();

        for (int jc = 0; jc < 32; jc++) {
            float* cur = (jc & 1) ? tile1 : tile0;
            float* nxt = (jc & 1) ? tile0 : tile1;

            float pre[8];
            if (jc < 31) {
                #pragma unroll
                for (int t = 0; t < 8; t++) {
                    const int e = t*512 + tid;
                    const int jl = e >> 8, i = e & 255;
                    pre[t] = Sb[(size_t)((jc+1)*16 + jl)*ND + i];
                }
            }

            if (kg < 13) {
                #pragma unroll 2
                for (int jj = 0; jj < 16; jj++) {
                    const int j = jc*16 + jj;
                    const ulonglong2 p01 = *(const ulonglong2*)(cur + jj*256 + i0);
                    const ulonglong2 p23 = *(const ulonglong2*)(cur + jj*256 + i0 + 4);
                    const u64 pa0 = p01.x, pa1 = p01.y, pa2 = p23.x, pa3 = p23.y;
                    const float4 qv = *(const float4*)(s_q + j*QP + kg*4);
                    const float4 tv = __ldg((const float4*)(Tb + j*QP + kg*4));
                    u64 bb;
                    bb = pack2(qv.x, qv.x);
                    ac1[0][0]=fma2(pa0,bb,ac1[0][0]); ac1[0][1]=fma2(pa1,bb,ac1[0][1]);
                    ac1[0][2]=fma2(pa2,bb,ac1[0][2]); ac1[0][3]=fma2(pa3,bb,ac1[0][3]);
                    bb = pack2(qv.y, qv.y);
                    ac1[1][0]=fma2(pa0,bb,ac1[1][0]); ac1[1][1]=fma2(pa1,bb,ac1[1][1]);
                    ac1[1][2]=fma2(pa2,bb,ac1[1][2]); ac1[1][3]=fma2(pa3,bb,ac1[1][3]);
                    bb = pack2(qv.z, qv.z);
                    ac1[2][0]=fma2(pa0,bb,ac1[2][0]); ac1[2][1]=fma2(pa1,bb,ac1[2][1]);
                    ac1[2][2]=fma2(pa2,bb,ac1[2][2]); ac1[2][3]=fma2(pa3,bb,ac1[2][3]);
                    bb = pack2(qv.w, qv.w);
                    ac1[3][0]=fma2(pa0,bb,ac1[3][0]); ac1[3][1]=fma2(pa1,bb,ac1[3][1]);
                    ac1[3][2]=fma2(pa2,bb,ac1[3][2]); ac1[3][3]=fma2(pa3,bb,ac1[3][3]);
                    bb = pack2(tv.x, tv.x);
                    ac2[0][0]=fma2(pa0,bb,ac2[0][0]); ac2[0][1]=fma2(pa1,bb,ac2[0][1]);
                    ac2[0][2]=fma2(pa2,bb,ac2[0][2]); ac2[0][3]=fma2(pa3,bb,ac2[0][3]);
                    bb = pack2(tv.y, tv.y);
                    ac2[1][0]=fma2(pa0,bb,ac2[1][0]); ac2[1][1]=fma2(pa1,bb,ac2[1][1]);
                    ac2[1][2]=fma2(pa2,bb,ac2[1][2]); ac2[1][3]=fma2(pa3,bb,ac2[1][3]);
                    bb = pack2(tv.z, tv.z);
                    ac2[2][0]=fma2(pa0,bb,ac2[2][0]); ac2[2][1]=fma2(pa1,bb,ac2[2][1]);
                    ac2[2][2]=fma2(pa2,bb,ac2[2][2]); ac2[2][3]=fma2(pa3,bb,ac2[2][3]);
                    bb = pack2(tv.w, tv.w);
                    ac2[3][0]=fma2(pa0,bb,ac2[3][0]); ac2[3][1]=fma2(pa1,bb,ac2[3][1]);
                    ac2[3][2]=fma2(pa2,bb,ac2[3][2]); ac2[3][3]=fma2(pa3,bb,ac2[3][3]);
                }
            }

            if (jc < 31) {
                #pragma unroll
                for (int t = 0; t < 8; t++) {
                    const int e = t*512 + tid;
                    const int jl = e >> 8, i = e & 255;
                    const int j2 = (jc+1)*16 + jl;
                    nxt[jl*256 + i] = ex2(pre[t] - s_cmax[j2]) * s_cinv[j2];
                }
            }
            __syncthreads();
        }

        // ---------------- epilogue: [sen | aD2Q | sen*aD2Q | sen*aQ2D] ----------------
        if (kg < 13) {
            #pragma unroll
            for (int m = 0; m < 4; m++) {
                float2 u1[4], u2[4];
                #pragma unroll
                for (int k = 0; k < 4; k++) { u1[k] = unpack2(ac1[k][m]); u2[k] = unpack2(ac2[k][m]); }
                #pragma unroll
                for (int par = 0; par < 2; par++) {
                    const int i = i0 + 2*m + par;
                    float a1v[4], a2v[4];
                    #pragma unroll
                    for (int k = 0; k < 4; k++) {
                        a1v[k] = par ? u1[k].y : u1[k].x;
                        a2v[k] = par ? u2[k].y : u2[k].x;
                    }
                    const float4 sv = *(const float4*)(s_sen + i*QP + kg*4);
                    float* orow = out + ((size_t)b*ND + i) * NOUT;
                    if (kg < 12) {
                        *(float4*)(orow + kg*4) = sv;
                        *(float2*)(orow +  50 + kg*4) = make_float2(a1v[0], a1v[1]);
                        *(float2*)(orow +  52 + kg*4) = make_float2(a1v[2], a1v[3]);
                        float4 p2; p2.x = sv.x*a1v[0]; p2.y = sv.y*a1v[1];
                                   p2.z = sv.z*a1v[2]; p2.w = sv.w*a1v[3];
                        *(float4*)(orow + 100 + kg*4) = p2;
                        *(float2*)(orow + 150 + kg*4) = make_float2(sv.x*a2v[0], sv.y*a2v[1]);
                        *(float2*)(orow + 152 + kg*4) = make_float2(sv.z*a2v[2], sv.w*a2v[3]);
                    } else {
                        *(float2*)(orow +  48) = make_float2(sv.x, sv.y);
                        *(float2*)(orow +  98) = make_float2(a1v[0], a1v[1]);
                        *(float2*)(orow + 148) = make_float2(sv.x*a1v[0], sv.y*a1v[1]);
                        *(float2*)(orow + 198) = make_float2(sv.x*a2v[0], sv.y*a2v[1]);
                    }
                }
            }
        }
    }
}

// ================= launch =================
extern "C" void kernel_launch(void* const* d_in, const int* in_sizes, int n_in,
                              void* d_out, int out_size)
{
    const float* query = nullptr;
    const float* doc   = nullptr;
    const float* Wp    = nullptr;
    for (int i = 0; i < n_in; i++) {
        if      (in_sizes[i] == 150)     Wp    = (const float*)d_in[i];
        else if (in_sizes[i] == NQ*NF)   query = (const float*)d_in[i];
        else                             doc   = (const float*)d_in[i];
    }

    static bool attr_done = false;
    if (!attr_done) {
        cudaFuncSetAttribute(cross_attn_main,
                             cudaFuncAttributeMaxDynamicSharedMemorySize, SMEM_BYTES);
        attr_done = true;
    }

    k_prep<<<2, 256>>>(query, Wp);
    cross_attn_main<<<512, 512, SMEM_BYTES>>>(doc, Wp, (float*)d_out);
}

// round 10
// speedup vs baseline: 2.1903x; 1.1976x over previous
#include <cuda_runtime.h>

#define NQ 512
#define ND 256
#define NF 50
#define QP 52
#define STP 260
#define NOUT 200
#define L2E 1.44269504088896341f

typedef unsigned long long u64;
typedef unsigned int u32;

// ---------------- global scratch (no allocations) ----------------
__device__ float g_S   [67108864];  // [b][j][i] S col-major (log2-scaled logits)
__device__ float g_T   [13631488];  // [b][j][52]
__device__ float g_qpad[26624];     // [512][52]: cols0..49 q, col50=1, col51=qterm*L2E

// ---------------- helpers ----------------
__device__ __forceinline__ u64 pack2(float x, float y) {
    u64 r; asm("mov.b64 %0, {%1, %2};" : "=l"(r) : "f"(x), "f"(y)); return r;
}
__device__ __forceinline__ u64 fma2(u64 a, u64 b, u64 c) {
    u64 d; asm("fma.rn.f32x2 %0, %1, %2, %3;" : "=l"(d) : "l"(a), "l"(b), "l"(c)); return d;
}
__device__ __forceinline__ float2 unpack2(u64 v) {
    float lo, hi; asm("mov.b64 {%0, %1}, %2;" : "=f"(lo), "=f"(hi) : "l"(v));
    return make_float2(lo, hi);
}
__device__ __forceinline__ float ex2(float x) {
    float y; asm("ex2.approx.ftz.f32 %0, %1;" : "=f"(y) : "f"(x)); return y;
}

// ================= K_prep: padded q with (log2e-scaled) qterm fold =================
__global__ __launch_bounds__(256)
void k_prep(const float* __restrict__ q, const float* __restrict__ W)
{
    const int j = blockIdx.x * 256 + threadIdx.x;
    float qr[NF];
    #pragma unroll
    for (int k = 0; k < NF; k++) qr[k] = __ldg(q + j*NF + k);
    float a = 0.f;
    #pragma unroll
    for (int k = 0; k < NF; k++) a += qr[k] * __ldg(W + 50 + k);
    float* dst = g_qpad + j*QP;
    #pragma unroll
    for (int k = 0; k < NF; k++) dst[k] = qr[k];
    dst[50] = 1.0f; dst[51] = a * L2E;
}

// ================= main monolith: 512 threads =================
#define SMEM_FLOATS (26624 + 13312 + 13520 + 152 + 512 + 256)
#define SMEM_BYTES  (SMEM_FLOATS * 4)

__global__ __launch_bounds__(512, 1)
void cross_attn_main(const float* __restrict__ doc, const float* __restrict__ W,
                     float* __restrict__ out)
{
    extern __shared__ float sm[];
    float* s_q     = sm;                       // [512][QP]
    float* s_sen   = s_q + 26624;              // [256][QP]
    float* s_senT  = s_sen + 13312;            // [52][STP]; aliased later (rpart / tiles)
    float* s_w     = s_senT + 13520;           // [152] (pre-scaled by log2e)
    float* s_cinv  = s_w + 152;                // [512]
    float* s_rinv  = s_cinv + 512;             // [256]
    // aliases of s_senT region (valid after pass1, with syncs):
    float* rpart   = s_senT;                   // [16][256] rowsum partials
    float* tile0   = s_senT;                   // [16][256] P chunk
    float* tile1   = s_senT + 4096;            // [16][256]
    float* tT0     = s_senT + 8192;            // [16][56]  T chunk
    float* tT1     = s_senT + 9088;            // [16][56]

    const int tid = threadIdx.x;               // 0..511
    const int b   = blockIdx.x;
    float* Sb = g_S + (size_t)b * NQ * ND;
    float* Tb = g_T + (size_t)b * NQ * QP;

    // ---------------- load phase ----------------
    if (tid < 150) s_w[tid] = __ldg(W + tid) * L2E;
    for (int x = tid; x < 512*13; x += 512) {
        const int j = x / 13, c = x - j*13;
        *(float4*)(s_q + j*QP + c*4) = __ldg((const float4*)(g_qpad + j*QP + c*4));
    }
    for (int idx = tid; idx < ND*NF; idx += 512) {
        const int i = idx / NF, k = idx - i*NF;
        s_sen[i*QP + k] = doc[(size_t)b*ND*NF + idx];
    }
    if (tid < 256) { s_sen[tid*QP + 50] = 0.f; s_sen[tid*QP + 51] = 0.f; }
    __syncthreads();

    // senT rows 0..49 (w3*log2e folded); row50 = senw1*log2e; row51 = ones
    for (int idx = tid; idx < 50*256; idx += 512) {
        const int k = idx >> 8, i = idx & 255;
        s_senT[k*STP + i] = s_sen[i*QP + k] * s_w[100 + k];
    }
    if (tid < 256) {
        const int i = tid;
        float a = 0.f;
        #pragma unroll
        for (int k = 0; k < NF; k++) a += s_sen[i*QP + k] * s_w[k];
        s_senT[50*STP + i] = a;
        s_senT[51*STP + i] = 1.0f;
    }
    __syncthreads();

    // ---------------- pass 1: S' GEMM + fused col/row SUMS (max-free softmax) --------
    const int tx = tid & 31, ty = tid >> 5;
    const int i0 = tx * 8;
    {
        float rs[8];
        #pragma unroll
        for (int u = 0; u < 8; u++) rs[u] = 0.f;

        for (int jc = 0; jc < 4; jc++) {
            u64 acc[8][4];
            #pragma unroll
            for (int jj = 0; jj < 8; jj++)
                #pragma unroll
                for (int m = 0; m < 4; m++) acc[jj][m] = 0ull;

            #pragma unroll 2
            for (int k = 0; k < 52; k += 2) {
                const ulonglong2 a00 = *(const ulonglong2*)(s_senT + k*STP + i0);
                const ulonglong2 a01 = *(const ulonglong2*)(s_senT + k*STP + i0 + 4);
                const ulonglong2 a10 = *(const ulonglong2*)(s_senT + (k+1)*STP + i0);
                const ulonglong2 a11 = *(const ulonglong2*)(s_senT + (k+1)*STP + i0 + 4);
                #pragma unroll
                for (int jj = 0; jj < 8; jj++) {
                    const int j = jc*128 + jj*16 + ty;
                    const float2 qf = *(const float2*)(s_q + j*QP + k);
                    const u64 b0 = pack2(qf.x, qf.x);
                    const u64 b1 = pack2(qf.y, qf.y);
                    acc[jj][0] = fma2(a00.x, b0, acc[jj][0]);
                    acc[jj][1] = fma2(a00.y, b0, acc[jj][1]);
                    acc[jj][2] = fma2(a01.x, b0, acc[jj][2]);
                    acc[jj][3] = fma2(a01.y, b0, acc[jj][3]);
                    acc[jj][0] = fma2(a10.x, b1, acc[jj][0]);
                    acc[jj][1] = fma2(a10.y, b1, acc[jj][1]);
                    acc[jj][2] = fma2(a11.x, b1, acc[jj][2]);
                    acc[jj][3] = fma2(a11.y, b1, acc[jj][3]);
                }
            }

            float loc[8];
            #pragma unroll
            for (int jj = 0; jj < 8; jj++) {
                const int j = jc*128 + jj*16 + ty;
                ulonglong2 v0; v0.x = acc[jj][0]; v0.y = acc[jj][1];
                ulonglong2 v1; v1.x = acc[jj][2]; v1.y = acc[jj][3];
                *(ulonglong2*)(Sb + (size_t)j*ND + i0)     = v0;
                *(ulonglong2*)(Sb + (size_t)j*ND + i0 + 4) = v1;
                const float2 f0 = unpack2(acc[jj][0]);
                const float2 f1 = unpack2(acc[jj][1]);
                const float2 f2 = unpack2(acc[jj][2]);
                const float2 f3 = unpack2(acc[jj][3]);
                const float e0 = ex2(f0.x), e1 = ex2(f0.y);
                const float e2 = ex2(f1.x), e3 = ex2(f1.y);
                const float e4 = ex2(f2.x), e5 = ex2(f2.y);
                const float e6 = ex2(f3.x), e7 = ex2(f3.y);
                rs[0] += e0; rs[1] += e1; rs[2] += e2; rs[3] += e3;
                rs[4] += e4; rs[5] += e5; rs[6] += e6; rs[7] += e7;
                loc[jj] = ((e0+e1)+(e2+e3)) + ((e4+e5)+(e6+e7));
            }
            // 8 interleaved butterflies for colsums
            #pragma unroll
            for (int o = 16; o > 0; o >>= 1) {
                #pragma unroll
                for (int jj = 0; jj < 8; jj++)
                    loc[jj] += __shfl_xor_sync(0xffffffffu, loc[jj], o);
            }
            #pragma unroll
            for (int jj = 0; jj < 8; jj++)
                if (tx == jj) s_cinv[jc*128 + jj*16 + ty] = 1.0f / loc[jj];
        }

        // rowsum partials -> smem (alias of s_senT; all reads done)
        __syncthreads();
        #pragma unroll
        for (int u = 0; u < 8; u++) rpart[ty*256 + i0 + u] = rs[u];
    }
    __syncthreads();
    if (tid < 256) {
        float s = 0.f;
        #pragma unroll
        for (int w = 0; w < 16; w++) s += rpart[w*256 + tid];
        s_rinv[tid] = 1.0f / s;
    }
    __syncthreads();

    // ---------------- pass 5: T[j][k] = sum_i ex2(S[j][i])*rinv[i]*sen[i][k] ------
    {
        const int j = tid;
        const float4* col4 = (const float4*)(Sb + (size_t)j*ND);
        u64 acc[26];
        #pragma unroll
        for (int c = 0; c < 26; c++) acc[c] = 0ull;

        #pragma unroll 2
        for (int i4 = 0; i4 < ND/4; i4++) {
            const float4 v4 = col4[i4];
            const float vv[4] = { v4.x, v4.y, v4.z, v4.w };
            #pragma unroll
            for (int u = 0; u < 4; u++) {
                const int i = i4*4 + u;
                const float p = ex2(vv[u]) * s_rinv[i];
                const u64 p2 = pack2(p, p);
                const ulonglong2* srow = (const ulonglong2*)(s_sen + i*QP);
                #pragma unroll
                for (int c = 0; c < 13; c++) {
                    const ulonglong2 sv = srow[c];
                    acc[2*c+0] = fma2(sv.x, p2, acc[2*c+0]);
                    acc[2*c+1] = fma2(sv.y, p2, acc[2*c+1]);
                }
            }
        }
        ulonglong2* tdst = (ulonglong2*)(Tb + j*QP);
        #pragma unroll
        for (int c = 0; c < 13; c++) {
            ulonglong2 v; v.x = acc[2*c]; v.y = acc[2*c+1];
            tdst[c] = v;
        }
    }
    __syncthreads();

    // ---------------- fused pass 4+6: P & T staged in SMEM, double-buffered ----------
    //   P[j][i] = ex2(S[j][i]) * cinv[j]
    //   aD2Q[i][k] = sum_j P[j][i]*q[j][k],  aQ2D[i][k] = sum_j P[j][i]*T[j][k]
    {
        const int kg = tid & 15, ig = tid >> 4;
        const int gi0 = ig * 8;
        // P staging coords: 2 float4 per thread per chunk (1024 float4 per chunk)
        const int jl1 = tid >> 6,        c1 = (tid & 63) << 2;
        const int jl2 = (tid + 512) >> 6, c2 = ((tid + 512) & 63) << 2;
        // T staging coords: 208 float4 per chunk
        const bool tload = (tid < 208);
        const int tjl = tid / 13, tc4 = (tid % 13) << 2;

        u64 ac1[4][4], ac2[4][4];
        #pragma unroll
        for (int k = 0; k < 4; k++)
            #pragma unroll
            for (int m = 0; m < 4; m++) { ac1[k][m] = 0ull; ac2[k][m] = 0ull; }

        // stage chunk 0
        {
            const float4 a  = *(const float4*)(Sb + (size_t)jl1*ND + c1);
            const float4 b2 = *(const float4*)(Sb + (size_t)jl2*ND + c2);
            const float ci1 = s_cinv[jl1], ci2 = s_cinv[jl2];
            float4 pa, pb;
            pa.x = ex2(a.x)*ci1;  pa.y = ex2(a.y)*ci1;
            pa.z = ex2(a.z)*ci1;  pa.w = ex2(a.w)*ci1;
            pb.x = ex2(b2.x)*ci2; pb.y = ex2(b2.y)*ci2;
            pb.z = ex2(b2.z)*ci2; pb.w = ex2(b2.w)*ci2;
            *(float4*)(tile0 + jl1*256 + c1) = pa;
            *(float4*)(tile0 + jl2*256 + c2) = pb;
            if (tload)
                *(float4*)(tT0 + tjl*56 + tc4) = *((const float4*)Tb + tid);
        }
        __syncthreads();

        for (int jc = 0; jc < 32; jc++) {
            float* cur  = (jc & 1) ? tile1 : tile0;
            float* nxt  = (jc & 1) ? tile0 : tile1;
            float* tcur = (jc & 1) ? tT1 : tT0;
            float* tnxt = (jc & 1) ? tT0 : tT1;

            float4 preA, preB, preT;
            if (jc < 31) {
                preA = *(const float4*)(Sb + (size_t)((jc+1)*16 + jl1)*ND + c1);
                preB = *(const float4*)(Sb + (size_t)((jc+1)*16 + jl2)*ND + c2);
                if (tload) preT = *((const float4*)Tb + (jc+1)*208 + tid);
            }

            if (kg < 13) {
                #pragma unroll 2
                for (int jj = 0; jj < 16; jj++) {
                    const int j = jc*16 + jj;
                    const ulonglong2 p01 = *(const ulonglong2*)(cur + jj*256 + gi0);
                    const ulonglong2 p23 = *(const ulonglong2*)(cur + jj*256 + gi0 + 4);
                    const u64 pa0 = p01.x, pa1 = p01.y, pa2 = p23.x, pa3 = p23.y;
                    const float4 qv = *(const float4*)(s_q + j*QP + kg*4);
                    const float4 tv = *(const float4*)(tcur + jj*56 + kg*4);
                    u64 bb;
                    bb = pack2(qv.x, qv.x);
                    ac1[0][0]=fma2(pa0,bb,ac1[0][0]); ac1[0][1]=fma2(pa1,bb,ac1[0][1]);
                    ac1[0][2]=fma2(pa2,bb,ac1[0][2]); ac1[0][3]=fma2(pa3,bb,ac1[0][3]);
                    bb = pack2(qv.y, qv.y);
                    ac1[1][0]=fma2(pa0,bb,ac1[1][0]); ac1[1][1]=fma2(pa1,bb,ac1[1][1]);
                    ac1[1][2]=fma2(pa2,bb,ac1[1][2]); ac1[1][3]=fma2(pa3,bb,ac1[1][3]);
                    bb = pack2(qv.z, qv.z);
                    ac1[2][0]=fma2(pa0,bb,ac1[2][0]); ac1[2][1]=fma2(pa1,bb,ac1[2][1]);
                    ac1[2][2]=fma2(pa2,bb,ac1[2][2]); ac1[2][3]=fma2(pa3,bb,ac1[2][3]);
                    bb = pack2(qv.w, qv.w);
                    ac1[3][0]=fma2(pa0,bb,ac1[3][0]); ac1[3][1]=fma2(pa1,bb,ac1[3][1]);
                    ac1[3][2]=fma2(pa2,bb,ac1[3][2]); ac1[3][3]=fma2(pa3,bb,ac1[3][3]);
                    bb = pack2(tv.x, tv.x);
                    ac2[0][0]=fma2(pa0,bb,ac2[0][0]); ac2[0][1]=fma2(pa1,bb,ac2[0][1]);
                    ac2[0][2]=fma2(pa2,bb,ac2[0][2]); ac2[0][3]=fma2(pa3,bb,ac2[0][3]);
                    bb = pack2(tv.y, tv.y);
                    ac2[1][0]=fma2(pa0,bb,ac2[1][0]); ac2[1][1]=fma2(pa1,bb,ac2[1][1]);
                    ac2[1][2]=fma2(pa2,bb,ac2[1][2]); ac2[1][3]=fma2(pa3,bb,ac2[1][3]);
                    bb = pack2(tv.z, tv.z);
                    ac2[2][0]=fma2(pa0,bb,ac2[2][0]); ac2[2][1]=fma2(pa1,bb,ac2[2][1]);
                    ac2[2][2]=fma2(pa2,bb,ac2[2][2]); ac2[2][3]=fma2(pa3,bb,ac2[2][3]);
                    bb = pack2(tv.w, tv.w);
                    ac2[3][0]=fma2(pa0,bb,ac2[3][0]); ac2[3][1]=fma2(pa1,bb,ac2[3][1]);
                    ac2[3][2]=fma2(pa2,bb,ac2[3][2]); ac2[3][3]=fma2(pa3,bb,ac2[3][3]);
                }
            }

            if (jc < 31) {
                const int j1 = (jc+1)*16 + jl1, j2 = (jc+1)*16 + jl2;
                const float ci1 = s_cinv[j1], ci2 = s_cinv[j2];
                float4 pa, pb;
                pa.x = ex2(preA.x)*ci1; pa.y = ex2(preA.y)*ci1;
                pa.z = ex2(preA.z)*ci1; pa.w = ex2(preA.w)*ci1;
                pb.x = ex2(preB.x)*ci2; pb.y = ex2(preB.y)*ci2;
                pb.z = ex2(preB.z)*ci2; pb.w = ex2(preB.w)*ci2;
                *(float4*)(nxt + jl1*256 + c1) = pa;
                *(float4*)(nxt + jl2*256 + c2) = pb;
                if (tload) *(float4*)(tnxt + tjl*56 + tc4) = preT;
            }
            __syncthreads();
        }

        // ---------------- epilogue: [sen | aD2Q | sen*aD2Q | sen*aQ2D] ----------------
        if (kg < 13) {
            #pragma unroll
            for (int m = 0; m < 4; m++) {
                float2 u1[4], u2[4];
                #pragma unroll
                for (int k = 0; k < 4; k++) { u1[k] = unpack2(ac1[k][m]); u2[k] = unpack2(ac2[k][m]); }
                #pragma unroll
                for (int par = 0; par < 2; par++) {
                    const int i = gi0 + 2*m + par;
                    float a1v[4], a2v[4];
                    #pragma unroll
                    for (int k = 0; k < 4; k++) {
                        a1v[k] = par ? u1[k].y : u1[k].x;
                        a2v[k] = par ? u2[k].y : u2[k].x;
                    }
                    const float4 sv = *(const float4*)(s_sen + i*QP + kg*4);
                    float* orow = out + ((size_t)b*ND + i) * NOUT;
                    if (kg < 12) {
                        *(float4*)(orow + kg*4) = sv;
                        *(float2*)(orow +  50 + kg*4) = make_float2(a1v[0], a1v[1]);
                        *(float2*)(orow +  52 + kg*4) = make_float2(a1v[2], a1v[3]);
                        float4 p2; p2.x = sv.x*a1v[0]; p2.y = sv.y*a1v[1];
                                   p2.z = sv.z*a1v[2]; p2.w = sv.w*a1v[3];
                        *(float4*)(orow + 100 + kg*4) = p2;
                        *(float2*)(orow + 150 + kg*4) = make_float2(sv.x*a2v[0], sv.y*a2v[1]);
                        *(float2*)(orow + 152 + kg*4) = make_float2(sv.z*a2v[2], sv.w*a2v[3]);
                    } else {
                        *(float2*)(orow +  48) = make_float2(sv.x, sv.y);
                        *(float2*)(orow +  98) = make_float2(a1v[0], a1v[1]);
                        *(float2*)(orow + 148) = make_float2(sv.x*a1v[0], sv.y*a1v[1]);
                        *(float2*)(orow + 198) = make_float2(sv.x*a2v[0], sv.y*a2v[1]);
                    }
                }
            }
        }
    }
}

// ================= launch =================
extern "C" void kernel_launch(void* const* d_in, const int* in_sizes, int n_in,
                              void* d_out, int out_size)
{
    const float* query = nullptr;
    const float* doc   = nullptr;
    const float* Wp    = nullptr;
    for (int i = 0; i < n_in; i++) {
        if      (in_sizes[i] == 150)     Wp    = (const float*)d_in[i];
        else if (in_sizes[i] == NQ*NF)   query = (const float*)d_in[i];
        else                             doc   = (const float*)d_in[i];
    }

    static bool attr_done = false;
    if (!attr_done) {
        cudaFuncSetAttribute(cross_attn_main,
                             cudaFuncAttributeMaxDynamicSharedMemorySize, SMEM_BYTES);
        attr_done = true;
    }

    k_prep<<<2, 256>>>(query, Wp);
    cross_attn_main<<<512, 512, SMEM_BYTES>>>(doc, Wp, (float*)d_out);
}

// round 12
// speedup vs baseline: 2.3260x; 1.0620x over previous
#include <cuda_runtime.h>

#define NQ 512
#define ND 256
#define NF 50
#define QP 52
#define STP 260
#define NOUT 200
#define L2E 1.44269504088896341f

typedef unsigned long long u64;
typedef unsigned int u32;

// ---------------- global scratch (no allocations) ----------------
__device__ float g_S   [67108864];  // [b][j][i] E = 2^(S*log2e)  col-major
__device__ float g_T   [13631488];  // [b][j][52]
__device__ float g_qpad[26624];     // [512][52]: cols0..49 q, col50=1, col51=qterm*L2E

// ---------------- helpers ----------------
__device__ __forceinline__ u64 pack2(float x, float y) {
    u64 r; asm("mov.b64 %0, {%1, %2};" : "=l"(r) : "f"(x), "f"(y)); return r;
}
__device__ __forceinline__ u64 fma2(u64 a, u64 b, u64 c) {
    u64 d; asm("fma.rn.f32x2 %0, %1, %2, %3;" : "=l"(d) : "l"(a), "l"(b), "l"(c)); return d;
}
__device__ __forceinline__ float2 unpack2(u64 v) {
    float lo, hi; asm("mov.b64 {%0, %1}, %2;" : "=f"(lo), "=f"(hi) : "l"(v));
    return make_float2(lo, hi);
}
__device__ __forceinline__ float ex2(float x) {
    float y; asm("ex2.approx.ftz.f32 %0, %1;" : "=f"(y) : "f"(x)); return y;
}

// ================= K_prep: padded q with (log2e-scaled) qterm fold =================
__global__ __launch_bounds__(256)
void k_prep(const float* __restrict__ q, const float* __restrict__ W)
{
    const int j = blockIdx.x * 256 + threadIdx.x;
    float qr[NF];
    #pragma unroll
    for (int k = 0; k < NF; k++) qr[k] = __ldg(q + j*NF + k);
    float a = 0.f;
    #pragma unroll
    for (int k = 0; k < NF; k++) a += qr[k] * __ldg(W + 50 + k);
    float* dst = g_qpad + j*QP;
    #pragma unroll
    for (int k = 0; k < NF; k++) dst[k] = qr[k];
    dst[50] = 1.0f; dst[51] = a * L2E;
}

// ================= main monolith: 512 threads =================
#define SMEM_FLOATS (26624 + 13312 + 13520 + 152 + 512 + 256)
#define SMEM_BYTES  (SMEM_FLOATS * 4)

__global__ __launch_bounds__(512, 1)
void cross_attn_main(const float* __restrict__ doc, const float* __restrict__ W,
                     float* __restrict__ out)
{
    extern __shared__ float sm[];
    float* s_q     = sm;                       // [512][QP]
    float* s_sen   = s_q + 26624;              // [256][QP]
    float* s_senT  = s_sen + 13312;            // [52][STP]; aliased later
    float* s_w     = s_senT + 13520;           // [152] (pre-scaled by log2e)
    float* s_cinv  = s_w + 152;                // [512]
    float* s_rinv  = s_cinv + 512;             // [256]
    float* rpart   = s_senT;                   // [16][256] rowsum partials
    float* tile0   = s_senT;                   // [16][256] P chunk
    float* tile1   = s_senT + 4096;            // [16][256]
    float* tT0     = s_senT + 8192;            // [16][56]  T chunk
    float* tT1     = s_senT + 9088;            // [16][56]

    const int tid = threadIdx.x;               // 0..511
    const int b   = blockIdx.x;
    float* Sb = g_S + (size_t)b * NQ * ND;     // holds E after pass1
    float* Tb = g_T + (size_t)b * NQ * QP;

    // ---------------- load phase ----------------
    if (tid < 150) s_w[tid] = __ldg(W + tid) * L2E;
    for (int x = tid; x < 512*13; x += 512) {
        const int j = x / 13, c = x - j*13;
        *(float4*)(s_q + j*QP + c*4) = __ldg((const float4*)(g_qpad + j*QP + c*4));
    }
    for (int idx = tid; idx < ND*NF; idx += 512) {
        const int i = idx / NF, k = idx - i*NF;
        s_sen[i*QP + k] = doc[(size_t)b*ND*NF + idx];
    }
    if (tid < 256) { s_sen[tid*QP + 50] = 0.f; s_sen[tid*QP + 51] = 0.f; }
    __syncthreads();

    // senT rows 0..49 (w3*log2e folded); row50 = senw1*log2e; row51 = ones
    for (int idx = tid; idx < 50*256; idx += 512) {
        const int k = idx >> 8, i = idx & 255;
        s_senT[k*STP + i] = s_sen[i*QP + k] * s_w[100 + k];
    }
    if (tid < 256) {
        const int i = tid;
        float a = 0.f;
        #pragma unroll
        for (int k = 0; k < NF; k++) a += s_sen[i*QP + k] * s_w[k];
        s_senT[50*STP + i] = a;
        s_senT[51*STP + i] = 1.0f;
    }
    __syncthreads();

    // ---------------- pass 1: S' GEMM -> store E = 2^S', fused col/row sums --------
    const int tx = tid & 31, ty = tid >> 5;
    const int i0 = tx * 8;
    {
        float rs[8];
        #pragma unroll
        for (int u = 0; u < 8; u++) rs[u] = 0.f;

        for (int jc = 0; jc < 4; jc++) {
            u64 acc[8][4];
            #pragma unroll
            for (int jj = 0; jj < 8; jj++)
                #pragma unroll
                for (int m = 0; m < 4; m++) acc[jj][m] = 0ull;

            #pragma unroll 2
            for (int k = 0; k < 52; k += 2) {
                const ulonglong2 a00 = *(const ulonglong2*)(s_senT + k*STP + i0);
                const ulonglong2 a01 = *(const ulonglong2*)(s_senT + k*STP + i0 + 4);
                const ulonglong2 a10 = *(const ulonglong2*)(s_senT + (k+1)*STP + i0);
                const ulonglong2 a11 = *(const ulonglong2*)(s_senT + (k+1)*STP + i0 + 4);
                #pragma unroll
                for (int jj = 0; jj < 8; jj++) {
                    const int j = jc*128 + jj*16 + ty;
                    const float2 qf = *(const float2*)(s_q + j*QP + k);
                    const u64 b0 = pack2(qf.x, qf.x);
                    const u64 b1 = pack2(qf.y, qf.y);
                    acc[jj][0] = fma2(a00.x, b0, acc[jj][0]);
                    acc[jj][1] = fma2(a00.y, b0, acc[jj][1]);
                    acc[jj][2] = fma2(a01.x, b0, acc[jj][2]);
                    acc[jj][3] = fma2(a01.y, b0, acc[jj][3]);
                    acc[jj][0] = fma2(a10.x, b1, acc[jj][0]);
                    acc[jj][1] = fma2(a10.y, b1, acc[jj][1]);
                    acc[jj][2] = fma2(a11.x, b1, acc[jj][2]);
                    acc[jj][3] = fma2(a11.y, b1, acc[jj][3]);
                }
            }

            float loc[8];
            #pragma unroll
            for (int jj = 0; jj < 8; jj++) {
                const int j = jc*128 + jj*16 + ty;
                const float2 f0 = unpack2(acc[jj][0]);
                const float2 f1 = unpack2(acc[jj][1]);
                const float2 f2 = unpack2(acc[jj][2]);
                const float2 f3 = unpack2(acc[jj][3]);
                const float e0 = ex2(f0.x), e1 = ex2(f0.y);
                const float e2 = ex2(f1.x), e3 = ex2(f1.y);
                const float e4 = ex2(f2.x), e5 = ex2(f2.y);
                const float e6 = ex2(f3.x), e7 = ex2(f3.y);
                ulonglong2 v0; v0.x = pack2(e0, e1); v0.y = pack2(e2, e3);
                ulonglong2 v1; v1.x = pack2(e4, e5); v1.y = pack2(e6, e7);
                *(ulonglong2*)(Sb + (size_t)j*ND + i0)     = v0;   // store E
                *(ulonglong2*)(Sb + (size_t)j*ND + i0 + 4) = v1;
                rs[0] += e0; rs[1] += e1; rs[2] += e2; rs[3] += e3;
                rs[4] += e4; rs[5] += e5; rs[6] += e6; rs[7] += e7;
                loc[jj] = ((e0+e1)+(e2+e3)) + ((e4+e5)+(e6+e7));
            }
            #pragma unroll
            for (int o = 16; o > 0; o >>= 1) {
                #pragma unroll
                for (int jj = 0; jj < 8; jj++)
                    loc[jj] += __shfl_xor_sync(0xffffffffu, loc[jj], o);
            }
            #pragma unroll
            for (int jj = 0; jj < 8; jj++)
                if (tx == jj) s_cinv[jc*128 + jj*16 + ty] = 1.0f / loc[jj];
        }

        __syncthreads();
        #pragma unroll
        for (int u = 0; u < 8; u++) rpart[ty*256 + i0 + u] = rs[u];
    }
    __syncthreads();
    if (tid < 256) {
        float s = 0.f;
        #pragma unroll
        for (int w = 0; w < 16; w++) s += rpart[w*256 + tid];
        s_rinv[tid] = 1.0f / s;
    }
    __syncthreads();

    // ---------------- pass 5: T[j][k] = sum_i E[j][i]*rinv[i]*sen[i][k] ------
    // 2 threads per column-pair: thread handles cols (jp, jp+256) x half-k (overlap trick)
    {
        const int jp = tid & 255, h = tid >> 8;
        const int koff = h ? 24 : 0;                 // quads: h0 k0..27, h1 k24..51
        const float4* colA = (const float4*)(Sb + (size_t)jp*ND);
        const float4* colB = (const float4*)(Sb + (size_t)(jp + 256)*ND);
        u64 accA[14], accB[14];
        #pragma unroll
        for (int d = 0; d < 14; d++) { accA[d] = 0ull; accB[d] = 0ull; }

        #pragma unroll 2
        for (int i4 = 0; i4 < ND/4; i4++) {
            const float4 ea = colA[i4];
            const float4 eb = colB[i4];
            const float eav[4] = { ea.x, ea.y, ea.z, ea.w };
            const float ebv[4] = { eb.x, eb.y, eb.z, eb.w };
            #pragma unroll
            for (int u = 0; u < 4; u++) {
                const int i = i4*4 + u;
                const float ri = s_rinv[i];
                const float p0 = eav[u] * ri;
                const float p1 = ebv[u] * ri;
                const u64 b0 = pack2(p0, p0);
                const u64 b1 = pack2(p1, p1);
                const ulonglong2* srow = (const ulonglong2*)(s_sen + i*QP + koff);
                #pragma unroll
                for (int c = 0; c < 7; c++) {
                    const ulonglong2 sv = srow[c];
                    accA[2*c+0] = fma2(sv.x, b0, accA[2*c+0]);
                    accA[2*c+1] = fma2(sv.y, b0, accA[2*c+1]);
                    accB[2*c+0] = fma2(sv.x, b1, accB[2*c+0]);
                    accB[2*c+1] = fma2(sv.y, b1, accB[2*c+1]);
                }
            }
        }
        if (h == 0) {       // write features 0..27
            #pragma unroll
            for (int c = 0; c < 7; c++) {
                ulonglong2 vA; vA.x = accA[2*c]; vA.y = accA[2*c+1];
                ulonglong2 vB; vB.x = accB[2*c]; vB.y = accB[2*c+1];
                *(ulonglong2*)(Tb + jp*QP + 4*c)        = vA;
                *(ulonglong2*)(Tb + (jp+256)*QP + 4*c)  = vB;
            }
        } else {            // write features 28..51 (skip overlap 24..27)
            #pragma unroll
            for (int c = 0; c < 6; c++) {
                ulonglong2 vA; vA.x = accA[2+2*c]; vA.y = accA[3+2*c];
                ulonglong2 vB; vB.x = accB[2+2*c]; vB.y = accB[3+2*c];
                *(ulonglong2*)(Tb + jp*QP + 28 + 4*c)       = vA;
                *(ulonglong2*)(Tb + (jp+256)*QP + 28 + 4*c) = vB;
            }
        }
    }
    __syncthreads();

    // ---------------- fused pass 4+6: P & T staged in SMEM, software-pipelined -------
    //   P[j][i] = E[j][i] * cinv[j]
    //   aD2Q[i][k] = sum_j P[j][i]*q[j][k],  aQ2D[i][k] = sum_j P[j][i]*T[j][k]
    {
        const int kg = tid & 15, ig = tid >> 4;
        const int gi0 = ig * 8;
        const int jl1 = tid >> 6,         c1 = (tid & 63) << 2;
        const int jl2 = (tid + 512) >> 6, c2 = ((tid + 512) & 63) << 2;
        const bool tload = (tid < 208);
        const int tjl = tid / 13, tc4 = (tid % 13) << 2;

        u64 ac1[4][4], ac2[4][4];
        #pragma unroll
        for (int k = 0; k < 4; k++)
            #pragma unroll
            for (int m = 0; m < 4; m++) { ac1[k][m] = 0ull; ac2[k][m] = 0ull; }

        // stage chunk 0 (E * cinv)
        {
            const float4 a  = *(const float4*)(Sb + (size_t)jl1*ND + c1);
            const float4 b2 = *(const float4*)(Sb + (size_t)jl2*ND + c2);
            const float ci1 = s_cinv[jl1], ci2 = s_cinv[jl2];
            float4 pa, pb;
            pa.x = a.x*ci1;  pa.y = a.y*ci1;  pa.z = a.z*ci1;  pa.w = a.w*ci1;
            pb.x = b2.x*ci2; pb.y = b2.y*ci2; pb.z = b2.z*ci2; pb.w = b2.w*ci2;
            *(float4*)(tile0 + jl1*256 + c1) = pa;
            *(float4*)(tile0 + jl2*256 + c2) = pb;
            if (tload)
                *(float4*)(tT0 + tjl*56 + tc4) = *((const float4*)Tb + tid);
        }
        __syncthreads();

        for (int jc = 0; jc < 32; jc++) {
            float* cur  = (jc & 1) ? tile1 : tile0;
            float* nxt  = (jc & 1) ? tile0 : tile1;
            float* tcur = (jc & 1) ? tT1 : tT0;
            float* tnxt = (jc & 1) ? tT0 : tT1;

            float4 preA, preB, preT;
            if (jc < 31) {
                preA = *(const float4*)(Sb + (size_t)((jc+1)*16 + jl1)*ND + c1);
                preB = *(const float4*)(Sb + (size_t)((jc+1)*16 + jl2)*ND + c2);
                if (tload) preT = *((const float4*)Tb + (jc+1)*208 + tid);
            }

            if (kg < 13) {
                // software-pipelined inner loop: prefetch jj+1 operands
                ulonglong2 p01 = *(const ulonglong2*)(cur + gi0);
                ulonglong2 p23 = *(const ulonglong2*)(cur + gi0 + 4);
                float4 qv = *(const float4*)(s_q + (jc*16)*QP + kg*4);
                float4 tv = *(const float4*)(tcur + kg*4);
                #pragma unroll
                for (int jj = 0; jj < 16; jj++) {
                    ulonglong2 np01, np23; float4 nqv, ntv;
                    if (jj < 15) {
                        np01 = *(const ulonglong2*)(cur + (jj+1)*256 + gi0);
                        np23 = *(const ulonglong2*)(cur + (jj+1)*256 + gi0 + 4);
                        nqv  = *(const float4*)(s_q + (jc*16 + jj+1)*QP + kg*4);
                        ntv  = *(const float4*)(tcur + (jj+1)*56 + kg*4);
                    }
                    const u64 pa0 = p01.x, pa1 = p01.y, pa2 = p23.x, pa3 = p23.y;
                    u64 bb;
                    bb = pack2(qv.x, qv.x);
                    ac1[0][0]=fma2(pa0,bb,ac1[0][0]); ac1[0][1]=fma2(pa1,bb,ac1[0][1]);
                    ac1[0][2]=fma2(pa2,bb,ac1[0][2]); ac1[0][3]=fma2(pa3,bb,ac1[0][3]);
                    bb = pack2(qv.y, qv.y);
                    ac1[1][0]=fma2(pa0,bb,ac1[1][0]); ac1[1][1]=fma2(pa1,bb,ac1[1][1]);
                    ac1[1][2]=fma2(pa2,bb,ac1[1][2]); ac1[1][3]=fma2(pa3,bb,ac1[1][3]);
                    bb = pack2(qv.z, qv.z);
                    ac1[2][0]=fma2(pa0,bb,ac1[2][0]); ac1[2][1]=fma2(pa1,bb,ac1[2][1]);
                    ac1[2][2]=fma2(pa2,bb,ac1[2][2]); ac1[2][3]=fma2(pa3,bb,ac1[2][3]);
                    bb = pack2(qv.w, qv.w);
                    ac1[3][0]=fma2(pa0,bb,ac1[3][0]); ac1[3][1]=fma2(pa1,bb,ac1[3][1]);
                    ac1[3][2]=fma2(pa2,bb,ac1[3][2]); ac1[3][3]=fma2(pa3,bb,ac1[3][3]);
                    bb = pack2(tv.x, tv.x);
                    ac2[0][0]=fma2(pa0,bb,ac2[0][0]); ac2[0][1]=fma2(pa1,bb,ac2[0][1]);
                    ac2[0][2]=fma2(pa2,bb,ac2[0][2]); ac2[0][3]=fma2(pa3,bb,ac2[0][3]);
                    bb = pack2(tv.y, tv.y);
                    ac2[1][0]=fma2(pa0,bb,ac2[1][0]); ac2[1][1]=fma2(pa1,bb,ac2[1][1]);
                    ac2[1][2]=fma2(pa2,bb,ac2[1][2]); ac2[1][3]=fma2(pa3,bb,ac2[1][3]);
                    bb = pack2(tv.z, tv.z);
                    ac2[2][0]=fma2(pa0,bb,ac2[2][0]); ac2[2][1]=fma2(pa1,bb,ac2[2][1]);
                    ac2[2][2]=fma2(pa2,bb,ac2[2][2]); ac2[2][3]=fma2(pa3,bb,ac2[2][3]);
                    bb = pack2(tv.w, tv.w);
                    ac2[3][0]=fma2(pa0,bb,ac2[3][0]); ac2[3][1]=fma2(pa1,bb,ac2[3][1]);
                    ac2[3][2]=fma2(pa2,bb,ac2[3][2]); ac2[3][3]=fma2(pa3,bb,ac2[3][3]);
                    p01 = np01; p23 = np23; qv = nqv; tv = ntv;
                }
            }

            if (jc < 31) {
                const int j1 = (jc+1)*16 + jl1, j2 = (jc+1)*16 + jl2;
                const float ci1 = s_cinv[j1], ci2 = s_cinv[j2];
                float4 pa, pb;
                pa.x = preA.x*ci1; pa.y = preA.y*ci1;
                pa.z = preA.z*ci1; pa.w = preA.w*ci1;
                pb.x = preB.x*ci2; pb.y = preB.y*ci2;
                pb.z = preB.z*ci2; pb.w = preB.w*ci2;
                *(float4*)(nxt + jl1*256 + c1) = pa;
                *(float4*)(nxt + jl2*256 + c2) = pb;
                if (tload) *(float4*)(tnxt + tjl*56 + tc4) = preT;
            }
            __syncthreads();
        }

        // ---------------- epilogue: [sen | aD2Q | sen*aD2Q | sen*aQ2D] ----------------
        if (kg < 13) {
            #pragma unroll
            for (int m = 0; m < 4; m++) {
                float2 u1[4], u2[4];
                #pragma unroll
                for (int k = 0; k < 4; k++) { u1[k] = unpack2(ac1[k][m]); u2[k] = unpack2(ac2[k][m]); }
                #pragma unroll
                for (int par = 0; par < 2; par++) {
                    const int i = gi0 + 2*m + par;
                    float a1v[4], a2v[4];
                    #pragma unroll
                    for (int k = 0; k < 4; k++) {
                        a1v[k] = par ? u1[k].y : u1[k].x;
                        a2v[k] = par ? u2[k].y : u2[k].x;
                    }
                    const float4 sv = *(const float4*)(s_sen + i*QP + kg*4);
                    float* orow = out + ((size_t)b*ND + i) * NOUT;
                    if (kg < 12) {
                        *(float4*)(orow + kg*4) = sv;
                        *(float2*)(orow +  50 + kg*4) = make_float2(a1v[0], a1v[1]);
                        *(float2*)(orow +  52 + kg*4) = make_float2(a1v[2], a1v[3]);
                        float4 p2; p2.x = sv.x*a1v[0]; p2.y = sv.y*a1v[1];
                                   p2.z = sv.z*a1v[2]; p2.w = sv.w*a1v[3];
                        *(float4*)(orow + 100 + kg*4) = p2;
                        *(float2*)(orow + 150 + kg*4) = make_float2(sv.x*a2v[0], sv.y*a2v[1]);
                        *(float2*)(orow + 152 + kg*4) = make_float2(sv.z*a2v[2], sv.w*a2v[3]);
                    } else {
                        *(float2*)(orow +  48) = make_float2(sv.x, sv.y);
                        *(float2*)(orow +  98) = make_float2(a1v[0], a1v[1]);
                        *(float2*)(orow + 148) = make_float2(sv.x*a1v[0], sv.y*a1v[1]);
                        *(float2*)(orow + 198) = make_float2(sv.x*a2v[0], sv.y*a2v[1]);
                    }
                }
            }
        }
    }
}

// ================= launch =================
extern "C" void kernel_launch(void* const* d_in, const int* in_sizes, int n_in,
                              void* d_out, int out_size)
{
    const float* query = nullptr;
    const float* doc   = nullptr;
    const float* Wp    = nullptr;
    for (int i = 0; i < n_in; i++) {
        if      (in_sizes[i] == 150)     Wp    = (const float*)d_in[i];
        else if (in_sizes[i] == NQ*NF)   query = (const float*)d_in[i];
        else                             doc   = (const float*)d_in[i];
    }

    static bool attr_done = false;
    if (!attr_done) {
        cudaFuncSetAttribute(cross_attn_main,
                             cudaFuncAttributeMaxDynamicSharedMemorySize, SMEM_BYTES);
        attr_done = true;
    }

    k_prep<<<2, 256>>>(query, Wp);
    cross_attn_main<<<512, 512, SMEM_BYTES>>>(doc, Wp, (float*)d_out);
}

// round 14
// speedup vs baseline: 2.3511x; 1.0108x over previous
#include <cuda_runtime.h>

#define NQ 512
#define ND 256
#define NF 50
#define QP 52
#define STP 260
#define NOUT 200
#define L2E 1.44269504088896341f

typedef unsigned long long u64;
typedef unsigned int u32;

// ---------------- global scratch (no allocations) ----------------
__device__ float g_S   [67108864];  // [b][j][i] E = 2^(S*log2e)  col-major
__device__ float g_T   [13631488];  // [b][j][52]  T' = T * cinv[j]
__device__ float g_qpad[26624];     // [512][52]: cols0..49 q, col50=1, col51=qterm*L2E

// ---------------- helpers ----------------
__device__ __forceinline__ u64 pack2(float x, float y) {
    u64 r; asm("mov.b64 %0, {%1, %2};" : "=l"(r) : "f"(x), "f"(y)); return r;
}
__device__ __forceinline__ u64 fma2(u64 a, u64 b, u64 c) {
    u64 d; asm("fma.rn.f32x2 %0, %1, %2, %3;" : "=l"(d) : "l"(a), "l"(b), "l"(c)); return d;
}
__device__ __forceinline__ u64 mul2(u64 a, u64 b) {
    u64 d; asm("mul.rn.f32x2 %0, %1, %2;" : "=l"(d) : "l"(a), "l"(b)); return d;
}
__device__ __forceinline__ float2 unpack2(u64 v) {
    float lo, hi; asm("mov.b64 {%0, %1}, %2;" : "=f"(lo), "=f"(hi) : "l"(v));
    return make_float2(lo, hi);
}
__device__ __forceinline__ float ex2(float x) {
    float y; asm("ex2.approx.ftz.f32 %0, %1;" : "=f"(y) : "f"(x)); return y;
}
__device__ __forceinline__ void cp16(u32 dst, const void* src) {
    asm volatile("cp.async.cg.shared.global [%0], [%1], 16;" :: "r"(dst), "l"(src) : "memory");
}
__device__ __forceinline__ void cp_commit() {
    asm volatile("cp.async.commit_group;" ::: "memory");
}
__device__ __forceinline__ void cp_wait0() {
    asm volatile("cp.async.wait_group 0;" ::: "memory");
}

// ================= K_prep: padded q with (log2e-scaled) qterm fold =================
__global__ __launch_bounds__(256)
void k_prep(const float* __restrict__ q, const float* __restrict__ W)
{
    const int j = blockIdx.x * 256 + threadIdx.x;
    float qr[NF];
    #pragma unroll
    for (int k = 0; k < NF; k++) qr[k] = __ldg(q + j*NF + k);
    float a = 0.f;
    #pragma unroll
    for (int k = 0; k < NF; k++) a += qr[k] * __ldg(W + 50 + k);
    float* dst = g_qpad + j*QP;
    #pragma unroll
    for (int k = 0; k < NF; k++) dst[k] = qr[k];
    dst[50] = 1.0f; dst[51] = a * L2E;
}

// ================= main monolith: 512 threads =================
#define SMEM_FLOATS (26624 + 13312 + 13520 + 152 + 512 + 256)
#define SMEM_BYTES  (SMEM_FLOATS * 4)

__global__ __launch_bounds__(512, 1)
void cross_attn_main(const float* __restrict__ doc, const float* __restrict__ W,
                     float* __restrict__ out)
{
    extern __shared__ float sm[];
    float* s_q     = sm;                       // [512][QP] q; becomes q*cinv after stats
    float* s_sen   = s_q + 26624;              // [256][QP]
    float* s_senT  = s_sen + 13312;            // [52][STP]; aliased later
    float* s_w     = s_senT + 13520;           // [152] (pre-scaled by log2e)
    float* s_cinv  = s_w + 152;                // [512]
    float* s_rinv  = s_cinv + 512;             // [256]
    float* rpart   = s_senT;                   // [16][256] rowsum partials (alias)
    float* tile0   = s_senT;                   // [16][256] E chunk (alias)
    float* tile1   = s_senT + 4096;            // [16][256]
    float* tT0     = s_senT + 8192;            // [16][52]  T' chunk
    float* tT1     = s_senT + 9024;            // [16][52]

    const int tid = threadIdx.x;               // 0..511
    const int b   = blockIdx.x;
    float* Sb = g_S + (size_t)b * NQ * ND;     // holds E after pass1
    float* Tb = g_T + (size_t)b * NQ * QP;

    // ---------------- load phase ----------------
    if (tid < 150) s_w[tid] = __ldg(W + tid) * L2E;
    for (int x = tid; x < 512*13; x += 512) {
        const int j = x / 13, c = x - j*13;
        *(float4*)(s_q + j*QP + c*4) = __ldg((const float4*)(g_qpad + j*QP + c*4));
    }
    for (int idx = tid; idx < ND*NF; idx += 512) {
        const int i = idx / NF, k = idx - i*NF;
        s_sen[i*QP + k] = doc[(size_t)b*ND*NF + idx];
    }
    if (tid < 256) { s_sen[tid*QP + 50] = 0.f; s_sen[tid*QP + 51] = 0.f; }
    __syncthreads();

    // senT rows 0..49 (w3*log2e folded); row50 = senw1*log2e; row51 = ones
    for (int idx = tid; idx < 50*256; idx += 512) {
        const int k = idx >> 8, i = idx & 255;
        s_senT[k*STP + i] = s_sen[i*QP + k] * s_w[100 + k];
    }
    if (tid < 256) {
        const int i = tid;
        float a = 0.f;
        #pragma unroll
        for (int k = 0; k < NF; k++) a += s_sen[i*QP + k] * s_w[k];
        s_senT[50*STP + i] = a;
        s_senT[51*STP + i] = 1.0f;
    }
    __syncthreads();

    // ---------------- pass 1: S' GEMM -> store E = 2^S', fused col/row sums --------
    const int tx = tid & 31, ty = tid >> 5;
    const int i0 = tx * 8;
    {
        float rs[8];
        #pragma unroll
        for (int u = 0; u < 8; u++) rs[u] = 0.f;

        for (int jc = 0; jc < 4; jc++) {
            u64 acc[8][4];
            #pragma unroll
            for (int jj = 0; jj < 8; jj++)
                #pragma unroll
                for (int m = 0; m < 4; m++) acc[jj][m] = 0ull;

            #pragma unroll 2
            for (int k = 0; k < 52; k += 2) {
                const ulonglong2 a00 = *(const ulonglong2*)(s_senT + k*STP + i0);
                const ulonglong2 a01 = *(const ulonglong2*)(s_senT + k*STP + i0 + 4);
                const ulonglong2 a10 = *(const ulonglong2*)(s_senT + (k+1)*STP + i0);
                const ulonglong2 a11 = *(const ulonglong2*)(s_senT + (k+1)*STP + i0 + 4);
                #pragma unroll
                for (int jj = 0; jj < 8; jj++) {
                    const int j = jc*128 + jj*16 + ty;
                    const float2 qf = *(const float2*)(s_q + j*QP + k);
                    const u64 b0 = pack2(qf.x, qf.x);
                    const u64 b1 = pack2(qf.y, qf.y);
                    acc[jj][0] = fma2(a00.x, b0, acc[jj][0]);
                    acc[jj][1] = fma2(a00.y, b0, acc[jj][1]);
                    acc[jj][2] = fma2(a01.x, b0, acc[jj][2]);
                    acc[jj][3] = fma2(a01.y, b0, acc[jj][3]);
                    acc[jj][0] = fma2(a10.x, b1, acc[jj][0]);
                    acc[jj][1] = fma2(a10.y, b1, acc[jj][1]);
                    acc[jj][2] = fma2(a11.x, b1, acc[jj][2]);
                    acc[jj][3] = fma2(a11.y, b1, acc[jj][3]);
                }
            }

            float loc[8];
            #pragma unroll
            for (int jj = 0; jj < 8; jj++) {
                const int j = jc*128 + jj*16 + ty;
                const float2 f0 = unpack2(acc[jj][0]);
                const float2 f1 = unpack2(acc[jj][1]);
                const float2 f2 = unpack2(acc[jj][2]);
                const float2 f3 = unpack2(acc[jj][3]);
                const float e0 = ex2(f0.x), e1 = ex2(f0.y);
                const float e2 = ex2(f1.x), e3 = ex2(f1.y);
                const float e4 = ex2(f2.x), e5 = ex2(f2.y);
                const float e6 = ex2(f3.x), e7 = ex2(f3.y);
                ulonglong2 v0; v0.x = pack2(e0, e1); v0.y = pack2(e2, e3);
                ulonglong2 v1; v1.x = pack2(e4, e5); v1.y = pack2(e6, e7);
                *(ulonglong2*)(Sb + (size_t)j*ND + i0)     = v0;   // store E
                *(ulonglong2*)(Sb + (size_t)j*ND + i0 + 4) = v1;
                rs[0] += e0; rs[1] += e1; rs[2] += e2; rs[3] += e3;
                rs[4] += e4; rs[5] += e5; rs[6] += e6; rs[7] += e7;
                loc[jj] = ((e0+e1)+(e2+e3)) + ((e4+e5)+(e6+e7));
            }
            #pragma unroll
            for (int o = 16; o > 0; o >>= 1) {
                #pragma unroll
                for (int jj = 0; jj < 8; jj++)
                    loc[jj] += __shfl_xor_sync(0xffffffffu, loc[jj], o);
            }
            #pragma unroll
            for (int jj = 0; jj < 8; jj++)
                if (tx == jj) s_cinv[jc*128 + jj*16 + ty] = 1.0f / loc[jj];
        }

        __syncthreads();
        #pragma unroll
        for (int u = 0; u < 8; u++) rpart[ty*256 + i0 + u] = rs[u];
    }
    __syncthreads();

    // rowsum finalize + q' = q*cinv fold
    if (tid < 256) {
        float s = 0.f;
        #pragma unroll
        for (int w = 0; w < 16; w++) s += rpart[w*256 + tid];
        s_rinv[tid] = 1.0f / s;
    }
    {
        const int j = tid;
        const float ci = s_cinv[j];
        #pragma unroll
        for (int c = 0; c < 13; c++) {
            float4 v = *(float4*)(s_q + j*QP + c*4);
            v.x *= ci; v.y *= ci; v.z *= ci; v.w *= ci;
            *(float4*)(s_q + j*QP + c*4) = v;
        }
    }
    __syncthreads();

    // ---------------- pass 5: T'[j][k] = cinv[j]*sum_i E[j][i]*rinv[i]*sen[i][k] ----
    // 2 threads per column-pair: cols (jp, jp+256) x half-k (overlap trick)
    {
        const int jp = tid & 255, h = tid >> 8;
        const int koff = h ? 24 : 0;
        const float4* colA = (const float4*)(Sb + (size_t)jp*ND);
        const float4* colB = (const float4*)(Sb + (size_t)(jp + 256)*ND);
        u64 accA[14], accB[14];
        #pragma unroll
        for (int d = 0; d < 14; d++) { accA[d] = 0ull; accB[d] = 0ull; }

        #pragma unroll 2
        for (int i4 = 0; i4 < ND/4; i4++) {
            const float4 ea = colA[i4];
            const float4 eb = colB[i4];
            const float eav[4] = { ea.x, ea.y, ea.z, ea.w };
            const float ebv[4] = { eb.x, eb.y, eb.z, eb.w };
            #pragma unroll
            for (int u = 0; u < 4; u++) {
                const int i = i4*4 + u;
                const float ri = s_rinv[i];
                const float p0 = eav[u] * ri;
                const float p1 = ebv[u] * ri;
                const u64 b0 = pack2(p0, p0);
                const u64 b1 = pack2(p1, p1);
                const ulonglong2* srow = (const ulonglong2*)(s_sen + i*QP + koff);
                #pragma unroll
                for (int c = 0; c < 7; c++) {
                    const ulonglong2 sv = srow[c];
                    accA[2*c+0] = fma2(sv.x, b0, accA[2*c+0]);
                    accA[2*c+1] = fma2(sv.y, b0, accA[2*c+1]);
                    accB[2*c+0] = fma2(sv.x, b1, accB[2*c+0]);
                    accB[2*c+1] = fma2(sv.y, b1, accB[2*c+1]);
                }
            }
        }
        const float ciA = s_cinv[jp], ciB = s_cinv[jp + 256];
        const u64 cA = pack2(ciA, ciA), cB = pack2(ciB, ciB);
        #pragma unroll
        for (int d = 0; d < 14; d++) { accA[d] = mul2(accA[d], cA); accB[d] = mul2(accB[d], cB); }
        if (h == 0) {       // features 0..27
            #pragma unroll
            for (int c = 0; c < 7; c++) {
                ulonglong2 vA; vA.x = accA[2*c]; vA.y = accA[2*c+1];
                ulonglong2 vB; vB.x = accB[2*c]; vB.y = accB[2*c+1];
                *(ulonglong2*)(Tb + jp*QP + 4*c)        = vA;
                *(ulonglong2*)(Tb + (jp+256)*QP + 4*c)  = vB;
            }
        } else {            // features 28..51 (skip overlap 24..27)
            #pragma unroll
            for (int c = 0; c < 6; c++) {
                ulonglong2 vA; vA.x = accA[2+2*c]; vA.y = accA[3+2*c];
                ulonglong2 vB; vB.x = accB[2+2*c]; vB.y = accB[3+2*c];
                *(ulonglong2*)(Tb + jp*QP + 28 + 4*c)       = vA;
                *(ulonglong2*)(Tb + (jp+256)*QP + 28 + 4*c) = vB;
            }
        }
    }
    __syncthreads();

    // ---------------- fused pass 4+6: cp.async-staged E & T', double-buffered -------
    //   aD2Q[i][k] = sum_j E[j][i]*q'[j][k],  aQ2D[i][k] = sum_j E[j][i]*T'[j][k]
    {
        const int kg = tid & 15, ig = tid >> 4;
        const int gi0 = ig * 8;
        // staging coords: 2 float4 per thread for E-chunk, 1 for T'-chunk (tid<208)
        const int jl1 = tid >> 6,         c1 = (tid & 63) << 2;
        const int jl2 = (tid + 512) >> 6, c2 = ((tid + 512) & 63) << 2;
        const bool tload = (tid < 208);
        const int tjl = tid / 13, tc4 = (tid % 13) << 2;

        const u32 t0a  = (u32)__cvta_generic_to_shared(tile0);
        const u32 t1a  = (u32)__cvta_generic_to_shared(tile1);
        const u32 tt0a = (u32)__cvta_generic_to_shared(tT0);
        const u32 tt1a = (u32)__cvta_generic_to_shared(tT1);

        u64 ac1[4][4], ac2[4][4];
        #pragma unroll
        for (int k = 0; k < 4; k++)
            #pragma unroll
            for (int m = 0; m < 4; m++) { ac1[k][m] = 0ull; ac2[k][m] = 0ull; }

        // stage chunk 0 via cp.async
        cp16(t0a + (jl1*256 + c1)*4, Sb + (size_t)jl1*ND + c1);
        cp16(t0a + (jl2*256 + c2)*4, Sb + (size_t)jl2*ND + c2);
        if (tload) cp16(tt0a + (tjl*52 + tc4)*4, Tb + tjl*QP + tc4);
        cp_commit();
        cp_wait0();
        __syncthreads();

        for (int jc = 0; jc < 32; jc++) {
            float* cur  = (jc & 1) ? tile1 : tile0;
            float* tcur = (jc & 1) ? tT1 : tT0;

            if (jc < 31) {   // issue next chunk's async copies (land during compute)
                const u32 na  = (jc & 1) ? t0a  : t1a;
                const u32 nta = (jc & 1) ? tt0a : tt1a;
                const int jb = (jc + 1) * 16;
                cp16(na + (jl1*256 + c1)*4, Sb + (size_t)(jb + jl1)*ND + c1);
                cp16(na + (jl2*256 + c2)*4, Sb + (size_t)(jb + jl2)*ND + c2);
                if (tload) cp16(nta + (tjl*52 + tc4)*4, Tb + (jb + tjl)*QP + tc4);
                cp_commit();
            }

            if (kg < 13) {
                // software-pipelined inner loop over 16 j
                ulonglong2 p01 = *(const ulonglong2*)(cur + gi0);
                ulonglong2 p23 = *(const ulonglong2*)(cur + gi0 + 4);
                float4 qv = *(const float4*)(s_q + (jc*16)*QP + kg*4);
                float4 tv = *(const float4*)(tcur + kg*4);
                #pragma unroll
                for (int jj = 0; jj < 16; jj++) {
                    ulonglong2 np01, np23; float4 nqv, ntv;
                    if (jj < 15) {
                        np01 = *(const ulonglong2*)(cur + (jj+1)*256 + gi0);
                        np23 = *(const ulonglong2*)(cur + (jj+1)*256 + gi0 + 4);
                        nqv  = *(const float4*)(s_q + (jc*16 + jj+1)*QP + kg*4);
                        ntv  = *(const float4*)(tcur + (jj+1)*52 + kg*4);
                    }
                    const u64 pa0 = p01.x, pa1 = p01.y, pa2 = p23.x, pa3 = p23.y;
                    u64 bb;
                    bb = pack2(qv.x, qv.x);
                    ac1[0][0]=fma2(pa0,bb,ac1[0][0]); ac1[0][1]=fma2(pa1,bb,ac1[0][1]);
                    ac1[0][2]=fma2(pa2,bb,ac1[0][2]); ac1[0][3]=fma2(pa3,bb,ac1[0][3]);
                    bb = pack2(qv.y, qv.y);
                    ac1[1][0]=fma2(pa0,bb,ac1[1][0]); ac1[1][1]=fma2(pa1,bb,ac1[1][1]);
                    ac1[1][2]=fma2(pa2,bb,ac1[1][2]); ac1[1][3]=fma2(pa3,bb,ac1[1][3]);
                    bb = pack2(qv.z, qv.z);
                    ac1[2][0]=fma2(pa0,bb,ac1[2][0]); ac1[2][1]=fma2(pa1,bb,ac1[2][1]);
                    ac1[2][2]=fma2(pa2,bb,ac1[2][2]); ac1[2][3]=fma2(pa3,bb,ac1[2][3]);
                    bb = pack2(qv.w, qv.w);
                    ac1[3][0]=fma2(pa0,bb,ac1[3][0]); ac1[3][1]=fma2(pa1,bb,ac1[3][1]);
                    ac1[3][2]=fma2(pa2,bb,ac1[3][2]); ac1[3][3]=fma2(pa3,bb,ac1[3][3]);
                    bb = pack2(tv.x, tv.x);
                    ac2[0][0]=fma2(pa0,bb,ac2[0][0]); ac2[0][1]=fma2(pa1,bb,ac2[0][1]);
                    ac2[0][2]=fma2(pa2,bb,ac2[0][2]); ac2[0][3]=fma2(pa3,bb,ac2[0][3]);
                    bb = pack2(tv.y, tv.y);
                    ac2[1][0]=fma2(pa0,bb,ac2[1][0]); ac2[1][1]=fma2(pa1,bb,ac2[1][1]);
                    ac2[1][2]=fma2(pa2,bb,ac2[1][2]); ac2[1][3]=fma2(pa3,bb,ac2[1][3]);
                    bb = pack2(tv.z, tv.z);
                    ac2[2][0]=fma2(pa0,bb,ac2[2][0]); ac2[2][1]=fma2(pa1,bb,ac2[2][1]);
                    ac2[2][2]=fma2(pa2,bb,ac2[2][2]); ac2[2][3]=fma2(pa3,bb,ac2[2][3]);
                    bb = pack2(tv.w, tv.w);
                    ac2[3][0]=fma2(pa0,bb,ac2[3][0]); ac2[3][1]=fma2(pa1,bb,ac2[3][1]);
                    ac2[3][2]=fma2(pa2,bb,ac2[3][2]); ac2[3][3]=fma2(pa3,bb,ac2[3][3]);
                    p01 = np01; p23 = np23; qv = nqv; tv = ntv;
                }
            }

            if (jc < 31) cp_wait0();
            __syncthreads();
        }

        // ---------------- epilogue: [sen | aD2Q | sen*aD2Q | sen*aQ2D] ----------------
        if (kg < 13) {
            #pragma unroll
            for (int m = 0; m < 4; m++) {
                float2 u1[4], u2[4];
                #pragma unroll
                for (int k = 0; k < 4; k++) { u1[k] = unpack2(ac1[k][m]); u2[k] = unpack2(ac2[k][m]); }
                #pragma unroll
                for (int par = 0; par < 2; par++) {
                    const int i = gi0 + 2*m + par;
                    float a1v[4], a2v[4];
                    #pragma unroll
                    for (int k = 0; k < 4; k++) {
                        a1v[k] = par ? u1[k].y : u1[k].x;
                        a2v[k] = par ? u2[k].y : u2[k].x;
                    }
                    const float4 sv = *(const float4*)(s_sen + i*QP + kg*4);
                    float* orow = out + ((size_t)b*ND + i) * NOUT;
                    if (kg < 12) {
                        *(float4*)(orow + kg*4) = sv;
                        *(float2*)(orow +  50 + kg*4) = make_float2(a1v[0], a1v[1]);
                        *(float2*)(orow +  52 + kg*4) = make_float2(a1v[2], a1v[3]);
                        float4 p2; p2.x = sv.x*a1v[0]; p2.y = sv.y*a1v[1];
                                   p2.z = sv.z*a1v[2]; p2.w = sv.w*a1v[3];
                        *(float4*)(orow + 100 + kg*4) = p2;
                        *(float2*)(orow + 150 + kg*4) = make_float2(sv.x*a2v[0], sv.y*a2v[1]);
                        *(float2*)(orow + 152 + kg*4) = make_float2(sv.z*a2v[2], sv.w*a2v[3]);
                    } else {
                        *(float2*)(orow +  48) = make_float2(sv.x, sv.y);
                        *(float2*)(orow +  98) = make_float2(a1v[0], a1v[1]);
                        *(float2*)(orow + 148) = make_float2(sv.x*a1v[0], sv.y*a1v[1]);
                        *(float2*)(orow + 198) = make_float2(sv.x*a2v[0], sv.y*a2v[1]);
                    }
                }
            }
        }
    }
}

// ================= launch =================
extern "C" void kernel_launch(void* const* d_in, const int* in_sizes, int n_in,
                              void* d_out, int out_size)
{
    const float* query = nullptr;
    const float* doc   = nullptr;
    const float* Wp    = nullptr;
    for (int i = 0; i < n_in; i++) {
        if      (in_sizes[i] == 150)     Wp    = (const float*)d_in[i];
        else if (in_sizes[i] == NQ*NF)   query = (const float*)d_in[i];
        else                             doc   = (const float*)d_in[i];
    }

    static bool attr_done = false;
    if (!attr_done) {
        cudaFuncSetAttribute(cross_attn_main,
                             cudaFuncAttributeMaxDynamicSharedMemorySize, SMEM_BYTES);
        attr_done = true;
    }

    k_prep<<<2, 256>>>(query, Wp);
    cross_attn_main<<<512, 512, SMEM_BYTES>>>(doc, Wp, (float*)d_out);
}

// round 17
// speedup vs baseline: 2.4492x; 1.0417x over previous
#include <cuda_runtime.h>

#define NQ 512
#define ND 256
#define NF 50
#define QP 52
#define STP 260
#define NOUT 200
#define L2E 1.44269504088896341f
#define EP 20   // staged-E tile row stride (16B-aligned, LDS.128 conflict-free)

typedef unsigned long long u64;
typedef unsigned int u32;

// ---------------- global scratch (no allocations) ----------------
__device__ float g_S   [67108864];  // [b][j][i] E = 2^(S*log2e)  col-major
__device__ float g_T   [13631488];  // [b][j][52]  T' = T * cinv[j]
__device__ float g_qpad[26624];     // [512][52]: cols0..49 q, col50=1, col51=qterm*L2E

// ---------------- helpers ----------------
__device__ __forceinline__ u64 pack2(float x, float y) {
    u64 r; asm("mov.b64 %0, {%1, %2};" : "=l"(r) : "f"(x), "f"(y)); return r;
}
__device__ __forceinline__ u64 fma2(u64 a, u64 b, u64 c) {
    u64 d; asm("fma.rn.f32x2 %0, %1, %2, %3;" : "=l"(d) : "l"(a), "l"(b), "l"(c)); return d;
}
__device__ __forceinline__ u64 mul2(u64 a, u64 b) {
    u64 d; asm("mul.rn.f32x2 %0, %1, %2;" : "=l"(d) : "l"(a), "l"(b)); return d;
}
__device__ __forceinline__ float2 unpack2(u64 v) {
    float lo, hi; asm("mov.b64 {%0, %1}, %2;" : "=f"(lo), "=f"(hi) : "l"(v));
    return make_float2(lo, hi);
}
__device__ __forceinline__ float ex2(float x) {
    float y; asm("ex2.approx.ftz.f32 %0, %1;" : "=f"(y) : "f"(x)); return y;
}
__device__ __forceinline__ void cp16(u32 dst, const void* src) {
    asm volatile("cp.async.cg.shared.global [%0], [%1], 16;" :: "r"(dst), "l"(src) : "memory");
}
__device__ __forceinline__ void cp_commit() {
    asm volatile("cp.async.commit_group;" ::: "memory");
}
__device__ __forceinline__ void cp_wait0() {
    asm volatile("cp.async.wait_group 0;" ::: "memory");
}

// ================= K_prep: padded q with (log2e-scaled) qterm fold =================
__global__ __launch_bounds__(256)
void k_prep(const float* __restrict__ q, const float* __restrict__ W)
{
    const int j = blockIdx.x * 256 + threadIdx.x;
    float qr[NF];
    #pragma unroll
    for (int k = 0; k < NF; k++) qr[k] = __ldg(q + j*NF + k);
    float a = 0.f;
    #pragma unroll
    for (int k = 0; k < NF; k++) a += qr[k] * __ldg(W + 50 + k);
    float* dst = g_qpad + j*QP;
    #pragma unroll
    for (int k = 0; k < NF; k++) dst[k] = qr[k];
    dst[50] = 1.0f; dst[51] = a * L2E;
}

// ================= main monolith: 512 threads =================
#define SMEM_FLOATS (26624 + 13312 + 13520 + 152 + 512 + 256)
#define SMEM_BYTES  (SMEM_FLOATS * 4)

__global__ __launch_bounds__(512, 1)
void cross_attn_main(const float* __restrict__ doc, const float* __restrict__ W,
                     float* __restrict__ out)
{
    extern __shared__ float sm[];
    float* s_q     = sm;                       // [512][QP] q; becomes q*cinv after stats
    float* s_sen   = s_q + 26624;              // [256][QP]
    float* s_senT  = s_sen + 13312;            // [52][STP]; aliased later
    float* s_w     = s_senT + 13520;           // [152] (pre-scaled by log2e)
    float* s_cinv  = s_w + 152;                // [512]
    float* s_rinv  = s_cinv + 512;             // [256]
    float* rpart   = s_senT;                   // [16][256] rowsum partials (alias)
    float* stageE  = s_senT;                   // [512][EP] pass-5 E tile (alias, 10240 fl)
    float* tile0   = s_senT;                   // [16][256] E chunk (alias)
    float* tile1   = s_senT + 4096;            // [16][256]
    float* tT0     = s_senT + 8192;            // [16][52]  T' chunk
    float* tT1     = s_senT + 9024;            // [16][52]

    const int tid = threadIdx.x;               // 0..511
    const int b   = blockIdx.x;
    float* Sb = g_S + (size_t)b * NQ * ND;     // holds E after pass1
    float* Tb = g_T + (size_t)b * NQ * QP;

    // ---------------- load phase ----------------
    if (tid < 150) s_w[tid] = __ldg(W + tid) * L2E;
    for (int x = tid; x < 512*13; x += 512) {
        const int j = x / 13, c = x - j*13;
        *(float4*)(s_q + j*QP + c*4) = __ldg((const float4*)(g_qpad + j*QP + c*4));
    }
    for (int idx = tid; idx < ND*NF; idx += 512) {
        const int i = idx / NF, k = idx - i*NF;
        s_sen[i*QP + k] = doc[(size_t)b*ND*NF + idx];
    }
    if (tid < 256) { s_sen[tid*QP + 50] = 0.f; s_sen[tid*QP + 51] = 0.f; }
    __syncthreads();

    // senT rows 0..49 (w3*log2e folded); row50 = senw1*log2e; row51 = ones
    for (int idx = tid; idx < 50*256; idx += 512) {
        const int k = idx >> 8, i = idx & 255;
        s_senT[k*STP + i] = s_sen[i*QP + k] * s_w[100 + k];
    }
    if (tid < 256) {
        const int i = tid;
        float a = 0.f;
        #pragma unroll
        for (int k = 0; k < NF; k++) a += s_sen[i*QP + k] * s_w[k];
        s_senT[50*STP + i] = a;
        s_senT[51*STP + i] = 1.0f;
    }
    __syncthreads();

    // ---------------- pass 1: S' GEMM -> store E = 2^S', fused col/row sums --------
    const int tx = tid & 31, ty = tid >> 5;
    const int i0 = tx * 8;
    {
        float rs[8];
        #pragma unroll
        for (int u = 0; u < 8; u++) rs[u] = 0.f;

        for (int jc = 0; jc < 4; jc++) {
            u64 acc[8][4];
            #pragma unroll
            for (int jj = 0; jj < 8; jj++)
                #pragma unroll
                for (int m = 0; m < 4; m++) acc[jj][m] = 0ull;

            #pragma unroll 2
            for (int k = 0; k < 52; k += 2) {
                const ulonglong2 a00 = *(const ulonglong2*)(s_senT + k*STP + i0);
                const ulonglong2 a01 = *(const ulonglong2*)(s_senT + k*STP + i0 + 4);
                const ulonglong2 a10 = *(const ulonglong2*)(s_senT + (k+1)*STP + i0);
                const ulonglong2 a11 = *(const ulonglong2*)(s_senT + (k+1)*STP + i0 + 4);
                #pragma unroll
                for (int jj = 0; jj < 8; jj++) {
                    const int j = jc*128 + jj*16 + ty;
                    const float2 qf = *(const float2*)(s_q + j*QP + k);
                    const u64 b0 = pack2(qf.x, qf.x);
                    const u64 b1 = pack2(qf.y, qf.y);
                    acc[jj][0] = fma2(a00.x, b0, acc[jj][0]);
                    acc[jj][1] = fma2(a00.y, b0, acc[jj][1]);
                    acc[jj][2] = fma2(a01.x, b0, acc[jj][2]);
                    acc[jj][3] = fma2(a01.y, b0, acc[jj][3]);
                    acc[jj][0] = fma2(a10.x, b1, acc[jj][0]);
                    acc[jj][1] = fma2(a10.y, b1, acc[jj][1]);
                    acc[jj][2] = fma2(a11.x, b1, acc[jj][2]);
                    acc[jj][3] = fma2(a11.y, b1, acc[jj][3]);
                }
            }

            float loc[8];
            #pragma unroll
            for (int jj = 0; jj < 8; jj++) {
                const int j = jc*128 + jj*16 + ty;
                const float2 f0 = unpack2(acc[jj][0]);
                const float2 f1 = unpack2(acc[jj][1]);
                const float2 f2 = unpack2(acc[jj][2]);
                const float2 f3 = unpack2(acc[jj][3]);
                const float e0 = ex2(f0.x), e1 = ex2(f0.y);
                const float e2 = ex2(f1.x), e3 = ex2(f1.y);
                const float e4 = ex2(f2.x), e5 = ex2(f2.y);
                const float e6 = ex2(f3.x), e7 = ex2(f3.y);
                ulonglong2 v0; v0.x = pack2(e0, e1); v0.y = pack2(e2, e3);
                ulonglong2 v1; v1.x = pack2(e4, e5); v1.y = pack2(e6, e7);
                *(ulonglong2*)(Sb + (size_t)j*ND + i0)     = v0;   // store E
                *(ulonglong2*)(Sb + (size_t)j*ND + i0 + 4) = v1;
                rs[0] += e0; rs[1] += e1; rs[2] += e2; rs[3] += e3;
                rs[4] += e4; rs[5] += e5; rs[6] += e6; rs[7] += e7;
                loc[jj] = ((e0+e1)+(e2+e3)) + ((e4+e5)+(e6+e7));
            }
            #pragma unroll
            for (int o = 16; o > 0; o >>= 1) {
                #pragma unroll
                for (int jj = 0; jj < 8; jj++)
                    loc[jj] += __shfl_xor_sync(0xffffffffu, loc[jj], o);
            }
            #pragma unroll
            for (int jj = 0; jj < 8; jj++)
                if (tx == jj) s_cinv[jc*128 + jj*16 + ty] = 1.0f / loc[jj];
        }

        __syncthreads();
        #pragma unroll
        for (int u = 0; u < 8; u++) rpart[ty*256 + i0 + u] = rs[u];
    }
    __syncthreads();

    // rowsum finalize + q' = q*cinv fold
    if (tid < 256) {
        float s = 0.f;
        #pragma unroll
        for (int w = 0; w < 16; w++) s += rpart[w*256 + tid];
        s_rinv[tid] = 1.0f / s;
    }
    {
        const int j = tid;
        const float ci = s_cinv[j];
        #pragma unroll
        for (int c = 0; c < 13; c++) {
            float4 v = *(float4*)(s_q + j*QP + c*4);
            v.x *= ci; v.y *= ci; v.z *= ci; v.w *= ci;
            *(float4*)(s_q + j*QP + c*4) = v;
        }
    }
    __syncthreads();

    // ---------------- pass 5: T'[j][k] = cinv[j]*sum_i E[j][i]*rinv[i]*sen[i][k] ----
    // SMEM-staged i-chunks of E (coalesced); thread = column-pair (jp, jp+256) x half-k
    {
        const int jp = tid & 255, h = tid >> 8;
        const int koff = h ? 24 : 0;
        const u32 stA = (u32)__cvta_generic_to_shared(stageE);
        // staging task: consecutive threads cover consecutive quads of same row
        const int srow0 = tid >> 2,  sq0 = (tid & 3);          // tasks 0..511
        const int srow1 = srow0 + 128, srow2 = srow0 + 256, srow3 = srow0 + 384;

        u64 accA[14], accB[14];
        #pragma unroll
        for (int d = 0; d < 14; d++) { accA[d] = 0ull; accB[d] = 0ull; }

        for (int ic = 0; ic < 16; ic++) {
            // stage E[all 512 j][ic*16 .. ic*16+15] -> stageE[j][0..15] (stride EP)
            const int ib = ic * 16;
            cp16(stA + (srow0*EP + sq0*4)*4, Sb + (size_t)srow0*ND + ib + sq0*4);
            cp16(stA + (srow1*EP + sq0*4)*4, Sb + (size_t)srow1*ND + ib + sq0*4);
            cp16(stA + (srow2*EP + sq0*4)*4, Sb + (size_t)srow2*ND + ib + sq0*4);
            cp16(stA + (srow3*EP + sq0*4)*4, Sb + (size_t)srow3*ND + ib + sq0*4);
            cp_commit();
            cp_wait0();
            __syncthreads();

            // load this thread's 2 columns' 16 E values (LDS.128, stride-EP conflict-free)
            float4 eA[4], eB[4];
            #pragma unroll
            for (int qd = 0; qd < 4; qd++) {
                eA[qd] = *(const float4*)(stageE + jp*EP + qd*4);
                eB[qd] = *(const float4*)(stageE + (jp + 256)*EP + qd*4);
            }

            #pragma unroll
            for (int qd = 0; qd < 4; qd++) {
                const float eav[4] = { eA[qd].x, eA[qd].y, eA[qd].z, eA[qd].w };
                const float ebv[4] = { eB[qd].x, eB[qd].y, eB[qd].z, eB[qd].w };
                #pragma unroll
                for (int u = 0; u < 4; u++) {
                    const int i = ib + qd*4 + u;
                    const float ri = s_rinv[i];
                    const float p0 = eav[u] * ri;
                    const float p1 = ebv[u] * ri;
                    const u64 b0 = pack2(p0, p0);
                    const u64 b1 = pack2(p1, p1);
                    const ulonglong2* srow = (const ulonglong2*)(s_sen + i*QP + koff);
                    #pragma unroll
                    for (int c = 0; c < 7; c++) {
                        const ulonglong2 sv = srow[c];
                        accA[2*c+0] = fma2(sv.x, b0, accA[2*c+0]);
                        accA[2*c+1] = fma2(sv.y, b0, accA[2*c+1]);
                        accB[2*c+0] = fma2(sv.x, b1, accB[2*c+0]);
                        accB[2*c+1] = fma2(sv.y, b1, accB[2*c+1]);
                    }
                }
            }
            __syncthreads();
        }

        const float ciA = s_cinv[jp], ciB = s_cinv[jp + 256];
        const u64 cA = pack2(ciA, ciA), cB = pack2(ciB, ciB);
        #pragma unroll
        for (int d = 0; d < 14; d++) { accA[d] = mul2(accA[d], cA); accB[d] = mul2(accB[d], cB); }
        if (h == 0) {       // features 0..27
            #pragma unroll
            for (int c = 0; c < 7; c++) {
                ulonglong2 vA; vA.x = accA[2*c]; vA.y = accA[2*c+1];
                ulonglong2 vB; vB.x = accB[2*c]; vB.y = accB[2*c+1];
                *(ulonglong2*)(Tb + jp*QP + 4*c)        = vA;
                *(ulonglong2*)(Tb + (jp+256)*QP + 4*c)  = vB;
            }
        } else {            // features 28..51 (skip overlap 24..27)
            #pragma unroll
            for (int c = 0; c < 6; c++) {
                ulonglong2 vA; vA.x = accA[2+2*c]; vA.y = accA[3+2*c];
                ulonglong2 vB; vB.x = accB[2+2*c]; vB.y = accB[3+2*c];
                *(ulonglong2*)(Tb + jp*QP + 28 + 4*c)       = vA;
                *(ulonglong2*)(Tb + (jp+256)*QP + 28 + 4*c) = vB;
            }
        }
    }
    __syncthreads();

    // ---------------- fused pass 4+6: cp.async-staged E & T', double-buffered -------
    //   aD2Q[i][k] = sum_j E[j][i]*q'[j][k],  aQ2D[i][k] = sum_j E[j][i]*T'[j][k]
    {
        const int kg = tid & 15, ig = tid >> 4;
        const int gi0 = ig * 8;
        const int jl1 = tid >> 6,         c1 = (tid & 63) << 2;
        const int jl2 = (tid + 512) >> 6, c2 = ((tid + 512) & 63) << 2;
        const bool tload = (tid < 208);
        const int tjl = tid / 13, tc4 = (tid % 13) << 2;

        const u32 t0a  = (u32)__cvta_generic_to_shared(tile0);
        const u32 t1a  = (u32)__cvta_generic_to_shared(tile1);
        const u32 tt0a = (u32)__cvta_generic_to_shared(tT0);
        const u32 tt1a = (u32)__cvta_generic_to_shared(tT1);

        u64 ac1[4][4], ac2[4][4];
        #pragma unroll
        for (int k = 0; k < 4; k++)
            #pragma unroll
            for (int m = 0; m < 4; m++) { ac1[k][m] = 0ull; ac2[k][m] = 0ull; }

        // stage chunk 0 via cp.async
        cp16(t0a + (jl1*256 + c1)*4, Sb + (size_t)jl1*ND + c1);
        cp16(t0a + (jl2*256 + c2)*4, Sb + (size_t)jl2*ND + c2);
        if (tload) cp16(tt0a + (tjl*52 + tc4)*4, Tb + tjl*QP + tc4);
        cp_commit();
        cp_wait0();
        __syncthreads();

        for (int jc = 0; jc < 32; jc++) {
            float* cur  = (jc & 1) ? tile1 : tile0;
            float* tcur = (jc & 1) ? tT1 : tT0;

            if (jc < 31) {   // issue next chunk's async copies (land during compute)
                const u32 na  = (jc & 1) ? t0a  : t1a;
                const u32 nta = (jc & 1) ? tt0a : tt1a;
                const int jb = (jc + 1) * 16;
                cp16(na + (jl1*256 + c1)*4, Sb + (size_t)(jb + jl1)*ND + c1);
                cp16(na + (jl2*256 + c2)*4, Sb + (size_t)(jb + jl2)*ND + c2);
                if (tload) cp16(nta + (tjl*52 + tc4)*4, Tb + (jb + tjl)*QP + tc4);
                cp_commit();
            }

            if (kg < 13) {
                // software-pipelined inner loop over 16 j
                ulonglong2 p01 = *(const ulonglong2*)(cur + gi0);
                ulonglong2 p23 = *(const ulonglong2*)(cur + gi0 + 4);
                float4 qv = *(const float4*)(s_q + (jc*16)*QP + kg*4);
                float4 tv = *(const float4*)(tcur + kg*4);
                #pragma unroll
                for (int jj = 0; jj < 16; jj++) {
                    ulonglong2 np01, np23; float4 nqv, ntv;
                    if (jj < 15) {
                        np01 = *(const ulonglong2*)(cur + (jj+1)*256 + gi0);
                        np23 = *(const ulonglong2*)(cur + (jj+1)*256 + gi0 + 4);
                        nqv  = *(const float4*)(s_q + (jc*16 + jj+1)*QP + kg*4);
                        ntv  = *(const float4*)(tcur + (jj+1)*52 + kg*4);
                    }
                    const u64 pa0 = p01.x, pa1 = p01.y, pa2 = p23.x, pa3 = p23.y;
                    u64 bb;
                    bb = pack2(qv.x, qv.x);
                    ac1[0][0]=fma2(pa0,bb,ac1[0][0]); ac1[0][1]=fma2(pa1,bb,ac1[0][1]);
                    ac1[0][2]=fma2(pa2,bb,ac1[0][2]); ac1[0][3]=fma2(pa3,bb,ac1[0][3]);
                    bb = pack2(qv.y, qv.y);
                    ac1[1][0]=fma2(pa0,bb,ac1[1][0]); ac1[1][1]=fma2(pa1,bb,ac1[1][1]);
                    ac1[1][2]=fma2(pa2,bb,ac1[1][2]); ac1[1][3]=fma2(pa3,bb,ac1[1][3]);
                    bb = pack2(qv.z, qv.z);
                    ac1[2][0]=fma2(pa0,bb,ac1[2][0]); ac1[2][1]=fma2(pa1,bb,ac1[2][1]);
                    ac1[2][2]=fma2(pa2,bb,ac1[2][2]); ac1[2][3]=fma2(pa3,bb,ac1[2][3]);
                    bb = pack2(qv.w, qv.w);
                    ac1[3][0]=fma2(pa0,bb,ac1[3][0]); ac1[3][1]=fma2(pa1,bb,ac1[3][1]);
                    ac1[3][2]=fma2(pa2,bb,ac1[3][2]); ac1[3][3]=fma2(pa3,bb,ac1[3][3]);
                    bb = pack2(tv.x, tv.x);
                    ac2[0][0]=fma2(pa0,bb,ac2[0][0]); ac2[0][1]=fma2(pa1,bb,ac2[0][1]);
                    ac2[0][2]=fma2(pa2,bb,ac2[0][2]); ac2[0][3]=fma2(pa3,bb,ac2[0][3]);
                    bb = pack2(tv.y, tv.y);
                    ac2[1][0]=fma2(pa0,bb,ac2[1][0]); ac2[1][1]=fma2(pa1,bb,ac2[1][1]);
                    ac2[1][2]=fma2(pa2,bb,ac2[1][2]); ac2[1][3]=fma2(pa3,bb,ac2[1][3]);
                    bb = pack2(tv.z, tv.z);
                    ac2[2][0]=fma2(pa0,bb,ac2[2][0]); ac2[2][1]=fma2(pa1,bb,ac2[2][1]);
                    ac2[2][2]=fma2(pa2,bb,ac2[2][2]); ac2[2][3]=fma2(pa3,bb,ac2[2][3]);
                    bb = pack2(tv.w, tv.w);
                    ac2[3][0]=fma2(pa0,bb,ac2[3][0]); ac2[3][1]=fma2(pa1,bb,ac2[3][1]);
                    ac2[3][2]=fma2(pa2,bb,ac2[3][2]); ac2[3][3]=fma2(pa3,bb,ac2[3][3]);
                    p01 = np01; p23 = np23; qv = nqv; tv = ntv;
                }
            }

            if (jc < 31) cp_wait0();
            __syncthreads();
        }

        // ---------------- epilogue: [sen | aD2Q | sen*aD2Q | sen*aQ2D] ----------------
        if (kg < 13) {
            #pragma unroll
            for (int m = 0; m < 4; m++) {
                float2 u1[4], u2[4];
                #pragma unroll
                for (int k = 0; k < 4; k++) { u1[k] = unpack2(ac1[k][m]); u2[k] = unpack2(ac2[k][m]); }
                #pragma unroll
                for (int par = 0; par < 2; par++) {
                    const int i = gi0 + 2*m + par;
                    float a1v[4], a2v[4];
                    #pragma unroll
                    for (int k = 0; k < 4; k++) {
                        a1v[k] = par ? u1[k].y : u1[k].x;
                        a2v[k] = par ? u2[k].y : u2[k].x;
                    }
                    const float4 sv = *(const float4*)(s_sen + i*QP + kg*4);
                    float* orow = out + ((size_t)b*ND + i) * NOUT;
                    if (kg < 12) {
                        *(float4*)(orow + kg*4) = sv;
                        *(float2*)(orow +  50 + kg*4) = make_float2(a1v[0], a1v[1]);
                        *(float2*)(orow +  52 + kg*4) = make_float2(a1v[2], a1v[3]);
                        float4 p2; p2.x = sv.x*a1v[0]; p2.y = sv.y*a1v[1];
                                   p2.z = sv.z*a1v[2]; p2.w = sv.w*a1v[3];
                        *(float4*)(orow + 100 + kg*4) = p2;
                        *(float2*)(orow + 150 + kg*4) = make_float2(sv.x*a2v[0], sv.y*a2v[1]);
                        *(float2*)(orow + 152 + kg*4) = make_float2(sv.z*a2v[2], sv.w*a2v[3]);
                    } else {
                        *(float2*)(orow +  48) = make_float2(sv.x, sv.y);
                        *(float2*)(orow +  98) = make_float2(a1v[0], a1v[1]);
                        *(float2*)(orow + 148) = make_float2(sv.x*a1v[0], sv.y*a1v[1]);
                        *(float2*)(orow + 198) = make_float2(sv.x*a2v[0], sv.y*a2v[1]);
                    }
                }
            }
        }
    }
}

// ================= launch =================
extern "C" void kernel_launch(void* const* d_in, const int* in_sizes, int n_in,
                              void* d_out, int out_size)
{
    const float* query = nullptr;
    const float* doc   = nullptr;
    const float* Wp    = nullptr;
    for (int i = 0; i < n_in; i++) {
        if      (in_sizes[i] == 150)     Wp    = (const float*)d_in[i];
        else if (in_sizes[i] == NQ*NF)   query = (const float*)d_in[i];
        else                             doc   = (const float*)d_in[i];
    }

    static bool attr_done = false;
    if (!attr_done) {
        cudaFuncSetAttribute(cross_attn_main,
                             cudaFuncAttributeMaxDynamicSharedMemorySize, SMEM_BYTES);
        attr_done = true;
    }

    k_prep<<<2, 256>>>(query, Wp);
    cross_attn_main<<<512, 512, SMEM_BYTES>>>(doc, Wp, (float*)d_out);
}